// round 12
// baseline (speedup 1.0000x reference)
#include <cuda_runtime.h>
#include <cuda_bf16.h>
#include <math.h>
#include <stdint.h>

// ---------------- Problem constants ----------------
#define S      4096
#define HID    2048
#define NH     16
#define NKV    4
#define DD     128
#define FF     768
#define EPSV   1e-8f

#define OUT_ELEMS    (S * HID)
#define MEM_ELEMS    (NH * FF * DD)

// ---------------- Scratch (device globals; no allocation allowed) ----------------
__device__ __align__(16) float g_K  [S * 512];
__device__ __align__(16) float g_V  [S * 512];
__device__ __align__(16) float g_Q  [S * HID];
__device__ __align__(16) float g_MB [S * HID];
__device__ __align__(16) float g_G  [S * HID];
__device__ __align__(16) float g_NUM[(size_t)NH * S * DD];
__device__ __align__(16) float g_DELTA[4][(size_t)NH * FF * DD];
__device__ float g_DEN [NH * S];
__device__ float g_COEF[NH * S];
__device__ float g_DENA[NH * S];

// bf16 split operands
__device__ __align__(16) __nv_bfloat16 g_XH [S * HID];
__device__ __align__(16) __nv_bfloat16 g_XL [S * HID];
__device__ __align__(16) __nv_bfloat16 g_WqH[HID * HID], g_WqL[HID * HID];
__device__ __align__(16) __nv_bfloat16 g_WmH[HID * HID], g_WmL[HID * HID];
__device__ __align__(16) __nv_bfloat16 g_WgH[HID * HID], g_WgL[HID * HID];
__device__ __align__(16) __nv_bfloat16 g_WkH[512 * HID], g_WkL[512 * HID];
__device__ __align__(16) __nv_bfloat16 g_WvH[512 * HID], g_WvL[512 * HID];
__device__ __align__(16) __nv_bfloat16 g_MKH[(size_t)NKV * S * FF], g_MKL[(size_t)NKV * S * FF];
__device__ __align__(16) __nv_bfloat16 g_MQH[(size_t)NH * S * FF], g_MQL[(size_t)NH * S * FF];
__device__ __align__(16) __nv_bfloat16 g_MemH[MEM_ELEMS],  g_MemL[MEM_ELEMS];
__device__ __align__(16) __nv_bfloat16 g_NMemH[MEM_ELEMS], g_NMemL[MEM_ELEMS];
__device__ __align__(16) __nv_bfloat16 g_WMVH[(size_t)NH * S * DD], g_WMVL[(size_t)NH * S * DD];

// ---------------- helpers ----------------
__device__ __forceinline__ float warp_sum(float v) {
#pragma unroll
    for (int o = 16; o > 0; o >>= 1) v += __shfl_down_sync(0xffffffffu, v, o);
    return v;
}
__device__ __forceinline__ uint32_t smem_u32(const void* p) {
    uint32_t a;
    asm("{ .reg .u64 t; cvta.to.shared.u64 t, %1; cvt.u32.u64 %0, t; }"
        : "=r"(a) : "l"(p));
    return a;
}
__device__ __forceinline__ void cp_async16(uint32_t sa, const void* g) {
    asm volatile("cp.async.cg.shared.global [%0], [%1], 16;" :: "r"(sa), "l"(g) : "memory");
}
__device__ __forceinline__ void cp_commit() {
    asm volatile("cp.async.commit_group;" ::: "memory");
}
template<int N> __device__ __forceinline__ void cp_wait() {
    asm volatile("cp.async.wait_group %0;" :: "n"(N) : "memory");
}
__device__ __forceinline__ void ldm_x4(uint32_t* r, uint32_t addr) {
    asm volatile("ldmatrix.sync.aligned.m8n8.x4.shared.b16 {%0,%1,%2,%3}, [%4];"
                 : "=r"(r[0]), "=r"(r[1]), "=r"(r[2]), "=r"(r[3]) : "r"(addr));
}
__device__ __forceinline__ void ldm_x2(uint32_t* r, uint32_t addr) {
    asm volatile("ldmatrix.sync.aligned.m8n8.x2.shared.b16 {%0,%1}, [%2];"
                 : "=r"(r[0]), "=r"(r[1]) : "r"(addr));
}
__device__ __forceinline__ void ldm_x4_t(uint32_t* r, uint32_t addr) {
    asm volatile("ldmatrix.sync.aligned.m8n8.x4.trans.shared.b16 {%0,%1,%2,%3}, [%4];"
                 : "=r"(r[0]), "=r"(r[1]), "=r"(r[2]), "=r"(r[3]) : "r"(addr));
}
__device__ __forceinline__ void ldm_x2_t(uint32_t* r, uint32_t addr) {
    asm volatile("ldmatrix.sync.aligned.m8n8.x2.trans.shared.b16 {%0,%1}, [%2];"
                 : "=r"(r[0]), "=r"(r[1]) : "r"(addr));
}
__device__ __forceinline__ void mma_bf16(float* c, const uint32_t* a, const uint32_t* b) {
    asm volatile(
        "mma.sync.aligned.m16n8k16.row.col.f32.bf16.bf16.f32 "
        "{%0,%1,%2,%3}, {%4,%5,%6,%7}, {%8,%9}, {%0,%1,%2,%3};"
        : "+f"(c[0]), "+f"(c[1]), "+f"(c[2]), "+f"(c[3])
        : "r"(a[0]), "r"(a[1]), "r"(a[2]), "r"(a[3]), "r"(b[0]), "r"(b[1]));
}
__device__ __forceinline__ void split_write(float v, __nv_bfloat16* hp, __nv_bfloat16* lp,
                                            size_t idx) {
    __nv_bfloat16 h = __float2bfloat16(v);
    hp[idx] = h;
    lp[idx] = __float2bfloat16(v - __bfloat162float(h));
}

// ======================================================================
// fp32 -> bf16 hi/lo split conversion (vectorized x4)
// ======================================================================
__global__ void cvt_split(const float* __restrict__ x,
                          __nv_bfloat16* __restrict__ hi,
                          __nv_bfloat16* __restrict__ lo, int n4)
{
    int i = blockIdx.x * 256 + threadIdx.x;
    if (i >= n4) return;
    float4 v = ((const float4*)x)[i];
    __nv_bfloat16 h0 = __float2bfloat16(v.x), h1 = __float2bfloat16(v.y);
    __nv_bfloat16 h2 = __float2bfloat16(v.z), h3 = __float2bfloat16(v.w);
    __nv_bfloat16 l0 = __float2bfloat16(v.x - __bfloat162float(h0));
    __nv_bfloat16 l1 = __float2bfloat16(v.y - __bfloat162float(h1));
    __nv_bfloat16 l2 = __float2bfloat16(v.z - __bfloat162float(h2));
    __nv_bfloat16 l3 = __float2bfloat16(v.w - __bfloat162float(h3));
    __nv_bfloat162* hp = (__nv_bfloat162*)hi;
    __nv_bfloat162* lp = (__nv_bfloat162*)lo;
    hp[2 * i]     = __nv_bfloat162(h0, h1);
    hp[2 * i + 1] = __nv_bfloat162(h2, h3);
    lp[2 * i]     = __nv_bfloat162(l0, l1);
    lp[2 * i + 1] = __nv_bfloat162(l2, l3);
}

// ======================================================================
// Projection GEMM (bf16-split mma.sync): C = A @ W^T + bias (opt sigmoid)
// BM=128, BN template (128 or 256), BK=32, 256 threads, 8 warps (2 x 4),
// warp tile 64 x (BN/4). 3-stage cp.async pipeline, one barrier/chunk.
// ======================================================================
#define PJ_A_T 10240                        // 128 rows * 80B

template <int ACT, int BN>
__global__ __launch_bounds__(256, 1) void gemm_mma(
    const __nv_bfloat16* __restrict__ Ahi, const __nv_bfloat16* __restrict__ Alo,
    const __nv_bfloat16* __restrict__ Bhi, const __nv_bfloat16* __restrict__ Blo,
    const float* __restrict__ bias, float* __restrict__ C, int N, int K)
{
    extern __shared__ char sm[];
    constexpr int NT   = BN / 32;           // nt iterations per warp
    constexpr int B_T  = BN * 80;           // B tile bytes per half
    constexpr int STG  = 2 * PJ_A_T + 2 * B_T;
    const int tid  = threadIdx.x;
    const int lane = tid & 31;
    const int warp = tid >> 5;
    const int wm = warp >> 2;
    const int wn = warp & 3;
    const int bm = blockIdx.y * 128;
    const int bn = blockIdx.x * BN;
    const uint32_t sbase = smem_u32(sm);

    auto load_chunk = [&](int c, int st) {
        const int k0 = c << 5;
        const uint32_t stb = sbase + (uint32_t)st * STG;
#pragma unroll
        for (int half = 0; half < 2; ++half) {
            const __nv_bfloat16* src = (half ? Alo : Ahi) + (size_t)bm * K + k0;
#pragma unroll
            for (int rep = 0; rep < 2; ++rep) {
                int i = tid + rep * 256;
                int r = i >> 2, cc = i & 3;
                cp_async16(stb + (uint32_t)half * PJ_A_T + r * 80 + cc * 16,
                           src + (size_t)r * K + cc * 8);
            }
        }
#pragma unroll
        for (int half = 0; half < 2; ++half) {
            const __nv_bfloat16* src = (half ? Blo : Bhi) + (size_t)bn * K + k0;
#pragma unroll
            for (int rep = 0; rep < BN / 64; ++rep) {
                int i = tid + rep * 256;
                int r = i >> 2, cc = i & 3;
                cp_async16(stb + 2 * PJ_A_T + (uint32_t)half * B_T + r * 80 + cc * 16,
                           src + (size_t)r * K + cc * 8);
            }
        }
        cp_commit();
    };

    float acc[4][NT][4];
#pragma unroll
    for (int mt = 0; mt < 4; ++mt)
#pragma unroll
        for (int nt = 0; nt < NT; ++nt)
#pragma unroll
            for (int r = 0; r < 4; ++r) acc[mt][nt][r] = 0.f;

    const int NC = K >> 5;
    load_chunk(0, 0);
    load_chunk(1, 1);

    for (int c = 0; c < NC; ++c) {
        if (c + 1 < NC) cp_wait<1>(); else cp_wait<0>();
        __syncthreads();
        if (c + 2 < NC) load_chunk(c + 2, (c + 2) % 3);

        const uint32_t stb = sbase + (uint32_t)(c % 3) * STG;
#pragma unroll
        for (int k16 = 0; k16 < 2; ++k16) {
            uint32_t ah[4][4], al[4][4];
#pragma unroll
            for (int mt = 0; mt < 4; ++mt) {
                uint32_t rowa = (uint32_t)(wm * 64 + mt * 16 + (lane & 15));
                uint32_t coff = (uint32_t)((k16 * 16 + ((lane >> 4) << 3)) * 2);
                ldm_x4(ah[mt], stb + 0 * PJ_A_T + rowa * 80 + coff);
                ldm_x4(al[mt], stb + 1 * PJ_A_T + rowa * 80 + coff);
            }
#pragma unroll
            for (int nt = 0; nt < NT; ++nt) {
                uint32_t rowb = (uint32_t)(wn * (BN / 4) + nt * 8 + (lane & 7));
                uint32_t coff = (uint32_t)((k16 * 16 + (((lane >> 3) & 1) << 3)) * 2);
                uint32_t bh[2], bl[2];
                ldm_x2(bh, stb + 2 * PJ_A_T + 0 * B_T + rowb * 80 + coff);
                ldm_x2(bl, stb + 2 * PJ_A_T + 1 * B_T + rowb * 80 + coff);
#pragma unroll
                for (int mt = 0; mt < 4; ++mt) {
                    mma_bf16(acc[mt][nt], ah[mt], bh);
                    mma_bf16(acc[mt][nt], ah[mt], bl);
                    mma_bf16(acc[mt][nt], al[mt], bh);
                }
            }
        }
    }

    const int r0 = bm + wm * 64;
    const int c0 = bn + wn * (BN / 4);
    const int rl = lane >> 2;
    const int cl = (lane & 3) * 2;
#pragma unroll
    for (int mt = 0; mt < 4; ++mt) {
#pragma unroll
        for (int nt = 0; nt < NT; ++nt) {
            int col = c0 + nt * 8 + cl;
            float b0 = bias[col], b1 = bias[col + 1];
#pragma unroll
            for (int half = 0; half < 2; ++half) {
                int row = r0 + mt * 16 + rl + half * 8;
                float v0 = acc[mt][nt][2 * half + 0] + b0;
                float v1 = acc[mt][nt][2 * half + 1] + b1;
                if (ACT) {
                    v0 = 1.f / (1.f + expf(-v0));
                    v1 = 1.f / (1.f + expf(-v1));
                }
                *(float2*)(C + (size_t)row * N + col) = make_float2(v0, v1);
            }
        }
    }
}

#define PJ_SMEM_128 (3 * (2 * PJ_A_T + 2 * 128 * 80))   // 122880
#define PJ_SMEM_256 (3 * (2 * PJ_A_T + 2 * 256 * 80))   // 184320

// ======================================================================
// Skinny einsum GEMM (bf16-split): per head h,
// C[h][tile,128] = A[h/adiv][M,768] @ B[h][768,128].
// 3-stage pipeline. WITHDEN: fuse den_a[s] = dot(mq[s,:], nrm[h,:]) + EPS.
// ======================================================================
#define SK_AT_B 10240                 // A tile: 128 x 80B
#define SK_BT_B 8704                  // B tile: 32 x 272B
#define SK_STAGE (2*SK_AT_B + 2*SK_BT_B)   // 37888
#define SK_SMEM  (3 * SK_STAGE)            // 113664

template <int WITHDEN>
__global__ __launch_bounds__(256, 1) void gemm_skinny_mma(
    const __nv_bfloat16* __restrict__ AH, const __nv_bfloat16* __restrict__ AL,
    int adiv,
    const __nv_bfloat16* __restrict__ BH, const __nv_bfloat16* __restrict__ BL,
    float* __restrict__ Cbase, const float* __restrict__ nrm)
{
    extern __shared__ char sm[];
    const int tid  = threadIdx.x;
    const int lane = tid & 31;
    const int warp = tid >> 5;
    const int wm = warp >> 2;
    const int wn = warp & 3;
    const int h  = blockIdx.y;
    const int bm = blockIdx.x * 128;
    const uint32_t sbase = smem_u32(sm);

    const __nv_bfloat16* Ah = AH + (size_t)(h / adiv) * S * FF;
    const __nv_bfloat16* Al = AL + (size_t)(h / adiv) * S * FF;
    const __nv_bfloat16* Bh = BH + (size_t)h * FF * DD;
    const __nv_bfloat16* Bl = BL + (size_t)h * FF * DD;
    float* C = Cbase + (size_t)h * S * DD;

    auto load_chunk = [&](int c, int st) {
        const int k0 = c << 5;
        const uint32_t stb = sbase + (uint32_t)st * SK_STAGE;
        const __nv_bfloat16* asrc[2] = {Ah, Al};
        const __nv_bfloat16* bsrc[2] = {Bh, Bl};
#pragma unroll
        for (int half = 0; half < 2; ++half) {
#pragma unroll
            for (int rep = 0; rep < 2; ++rep) {
                int i = tid + rep * 256;
                int r = i >> 2, cc = i & 3;
                cp_async16(stb + (uint32_t)half * SK_AT_B + r * 80 + cc * 16,
                           asrc[half] + (size_t)(bm + r) * FF + k0 + cc * 8);
            }
#pragma unroll
            for (int rep = 0; rep < 2; ++rep) {
                int i = tid + rep * 256;
                int r = i >> 4, cc = i & 15;
                cp_async16(stb + 2 * SK_AT_B + (uint32_t)half * SK_BT_B + r * 272 + cc * 16,
                           bsrc[half] + (size_t)(k0 + r) * DD + cc * 8);
            }
        }
        cp_commit();
    };

    float acc[4][4][4];
#pragma unroll
    for (int mt = 0; mt < 4; ++mt)
#pragma unroll
        for (int nt = 0; nt < 4; ++nt)
#pragma unroll
            for (int r = 0; r < 4; ++r) acc[mt][nt][r] = 0.f;

    float den = 0.f;
    const float* nrh = WITHDEN ? (nrm + (size_t)h * FF) : nullptr;

    const int NC = FF >> 5;   // 24
    load_chunk(0, 0);
    load_chunk(1, 1);

    for (int c = 0; c < NC; ++c) {
        if (c + 1 < NC) cp_wait<1>(); else cp_wait<0>();
        __syncthreads();
        if (c + 2 < NC) load_chunk(c + 2, (c + 2) % 3);

        const int st = c % 3;
        const uint32_t stb = sbase + (uint32_t)st * SK_STAGE;

        if (WITHDEN) {
            // den partial: 2 threads per row, 16 cols each, from A smem tiles
            int r = tid >> 1, cs = (tid & 1) * 16;
            const __nv_bfloat16* ph =
                (const __nv_bfloat16*)(sm + (size_t)st * SK_STAGE + (size_t)r * 80);
            const __nv_bfloat16* pl =
                (const __nv_bfloat16*)(sm + (size_t)st * SK_STAGE + SK_AT_B + (size_t)r * 80);
            const float* nr = nrh + (c << 5) + cs;
#pragma unroll
            for (int j = 0; j < 16; ++j) {
                float v = __bfloat162float(ph[cs + j]) + __bfloat162float(pl[cs + j]);
                den = fmaf(v, nr[j], den);
            }
        }

#pragma unroll
        for (int k16 = 0; k16 < 2; ++k16) {
            uint32_t ah[4][4], al[4][4];
#pragma unroll
            for (int mt = 0; mt < 4; ++mt) {
                uint32_t rowa = (uint32_t)(wm * 64 + mt * 16 + (lane & 15));
                uint32_t coff = (uint32_t)((k16 * 16 + ((lane >> 4) << 3)) * 2);
                ldm_x4(ah[mt], stb + 0 * SK_AT_B + rowa * 80 + coff);
                ldm_x4(al[mt], stb + 1 * SK_AT_B + rowa * 80 + coff);
            }
#pragma unroll
            for (int nt = 0; nt < 4; ++nt) {
                uint32_t rowb = (uint32_t)(k16 * 16 + (lane & 15));
                uint32_t noff = (uint32_t)((wn * 32 + nt * 8) * 2);
                uint32_t bh[2], bl[2];
                ldm_x2_t(bh, stb + 2 * SK_AT_B + 0 * SK_BT_B + rowb * 272 + noff);
                ldm_x2_t(bl, stb + 2 * SK_AT_B + 1 * SK_BT_B + rowb * 272 + noff);
#pragma unroll
                for (int mt = 0; mt < 4; ++mt) {
                    mma_bf16(acc[mt][nt], ah[mt], bh);
                    mma_bf16(acc[mt][nt], ah[mt], bl);
                    mma_bf16(acc[mt][nt], al[mt], bh);
                }
            }
        }
    }

    if (WITHDEN) {
        den += __shfl_xor_sync(0xffffffffu, den, 1);
        if (!(tid & 1))
            g_DENA[(size_t)h * S + bm + (tid >> 1)] = den + EPSV;
    }

    const int r0 = bm + wm * 64;
    const int c0 = wn * 32;
    const int rl = lane >> 2;
    const int cl = (lane & 3) * 2;
#pragma unroll
    for (int mt = 0; mt < 4; ++mt)
#pragma unroll
        for (int nt = 0; nt < 4; ++nt) {
            int col = c0 + nt * 8 + cl;
#pragma unroll
            for (int half = 0; half < 2; ++half) {
                int row = r0 + mt * 16 + rl + half * 8;
                *(float2*)(C + (size_t)row * DD + col) =
                    make_float2(acc[mt][nt][2 * half], acc[mt][nt][2 * half + 1]);
            }
        }
}

// ======================================================================
// Delta GEMM (bf16-split, split-K=4), 3-stage pipeline:
// DELTA[part][h][f,d] = sum_{s in part} MK[h/4][s,f] * WMV[h][s,d]
// ======================================================================
#define DL_T_B 8704                   // 32 x 272B
#define DL_STAGE (4 * DL_T_B)         // 34816
#define DL_SMEM  (3 * DL_STAGE)       // 104448

__global__ __launch_bounds__(256, 1) void gemm_delta_mma()
{
    extern __shared__ char sm[];
    const int tid  = threadIdx.x;
    const int lane = tid & 31;
    const int warp = tid >> 5;
    const int wm = warp >> 2;
    const int wn = warp & 3;
    const int h    = blockIdx.z;
    const int part = blockIdx.y;
    const int f0   = blockIdx.x * 128;
    const uint32_t sbase = smem_u32(sm);

    const __nv_bfloat16* Ah = g_MKH + (size_t)(h >> 2) * S * FF;
    const __nv_bfloat16* Al = g_MKL + (size_t)(h >> 2) * S * FF;
    const __nv_bfloat16* Bh = g_WMVH + (size_t)h * S * DD;
    const __nv_bfloat16* Bl = g_WMVL + (size_t)h * S * DD;

    const int kbase = part * (S / 4);

    auto load_chunk = [&](int c, int st) {
        const int k0 = kbase + (c << 5);
        const uint32_t stb = sbase + (uint32_t)st * DL_STAGE;
        const __nv_bfloat16* srcs[4] = {Ah, Al, Bh, Bl};
#pragma unroll
        for (int tile = 0; tile < 4; ++tile) {
            const bool isA = tile < 2;
#pragma unroll
            for (int rep = 0; rep < 2; ++rep) {
                int i = tid + rep * 256;
                int r = i >> 4, cc = i & 15;
                const __nv_bfloat16* src = isA
                    ? srcs[tile] + (size_t)(k0 + r) * FF + f0 + cc * 8
                    : srcs[tile] + (size_t)(k0 + r) * DD + cc * 8;
                cp_async16(stb + (uint32_t)tile * DL_T_B + r * 272 + cc * 16, src);
            }
        }
        cp_commit();
    };

    float acc[4][4][4];
#pragma unroll
    for (int mt = 0; mt < 4; ++mt)
#pragma unroll
        for (int nt = 0; nt < 4; ++nt)
#pragma unroll
            for (int r = 0; r < 4; ++r) acc[mt][nt][r] = 0.f;

    const int NC = (S / 4) >> 5;   // 32
    load_chunk(0, 0);
    load_chunk(1, 1);

    for (int c = 0; c < NC; ++c) {
        if (c + 1 < NC) cp_wait<1>(); else cp_wait<0>();
        __syncthreads();
        if (c + 2 < NC) load_chunk(c + 2, (c + 2) % 3);

        const uint32_t stb = sbase + (uint32_t)(c % 3) * DL_STAGE;
#pragma unroll
        for (int k16 = 0; k16 < 2; ++k16) {
            uint32_t ah[4][4], al[4][4];
            uint32_t rowa = (uint32_t)(k16 * 16 + (lane & 7) + ((lane >> 4) << 3));
#pragma unroll
            for (int mt = 0; mt < 4; ++mt) {
                uint32_t cola = (uint32_t)((wm * 64 + mt * 16 + (((lane >> 3) & 1) << 3)) * 2);
                ldm_x4_t(ah[mt], stb + 0 * DL_T_B + rowa * 272 + cola);
                ldm_x4_t(al[mt], stb + 1 * DL_T_B + rowa * 272 + cola);
            }
#pragma unroll
            for (int nt = 0; nt < 4; ++nt) {
                uint32_t rowb = (uint32_t)(k16 * 16 + (lane & 15));
                uint32_t noff = (uint32_t)((wn * 32 + nt * 8) * 2);
                uint32_t bh[2], bl[2];
                ldm_x2_t(bh, stb + 2 * DL_T_B + rowb * 272 + noff);
                ldm_x2_t(bl, stb + 3 * DL_T_B + rowb * 272 + noff);
#pragma unroll
                for (int mt = 0; mt < 4; ++mt) {
                    mma_bf16(acc[mt][nt], ah[mt], bh);
                    mma_bf16(acc[mt][nt], ah[mt], bl);
                    mma_bf16(acc[mt][nt], al[mt], bh);
                }
            }
        }
    }

    float* Cp = g_DELTA[part] + (size_t)h * FF * DD;
    const int r0 = f0 + wm * 64;
    const int c0 = wn * 32;
    const int rl = lane >> 2;
    const int cl = (lane & 3) * 2;
#pragma unroll
    for (int mt = 0; mt < 4; ++mt)
#pragma unroll
        for (int nt = 0; nt < 4; ++nt) {
            int col = c0 + nt * 8 + cl;
#pragma unroll
            for (int half = 0; half < 2; ++half) {
                int row = r0 + mt * 16 + rl + half * 8;
                *(float2*)(Cp + (size_t)row * DD + col) =
                    make_float2(acc[mt][nt][2 * half], acc[mt][nt][2 * half + 1]);
            }
        }
}

// ======================================================================
// dpfp + L2-normalize, emits bf16 hi/lo. K variant fuses denom/coef.
// ======================================================================
template <bool WITHDEN>
__global__ __launch_bounds__(256) void dpfp_kernel(
    const float* __restrict__ X,
    __nv_bfloat16* __restrict__ outh, __nv_bfloat16* __restrict__ outl,
    const float* __restrict__ normv)
{
    const int s  = blockIdx.x;
    const int hh = blockIdx.y;
    const int nh = gridDim.y;
    const int t  = threadIdx.x;
    __shared__ float y[256];
    __shared__ float red[5][8];

    const float* x = X + ((size_t)s * nh + hh) * 128;
    float xv = (t < 128) ? x[t] : -x[t - 128];
    y[t] = fmaxf(xv, 0.f);
    __syncthreads();

    float yi = y[t];
    float m0 = yi * y[(t - 1) & 255];
    float m1 = yi * y[(t - 2) & 255];
    float m2 = yi * y[(t - 3) & 255];
    float ss = m0 * m0 + m1 * m1 + m2 * m2;

    float dd[4];
    if (WITHDEN) {
#pragma unroll
        for (int g = 0; g < 4; g++) {
            const float* nr = normv + (size_t)(4 * hh + g) * FF;
            dd[g] = m0 * nr[t] + m1 * nr[256 + t] + m2 * nr[512 + t];
        }
    }

    const int lane = t & 31, w = t >> 5;
    float r0 = warp_sum(ss);
    if (lane == 0) red[0][w] = r0;
    if (WITHDEN) {
#pragma unroll
        for (int g = 0; g < 4; g++) {
            float rg = warp_sum(dd[g]);
            if (lane == 0) red[1 + g][w] = rg;
        }
    }
    __syncthreads();

    float ssT = 0.f;
#pragma unroll
    for (int w2 = 0; w2 < 8; w2++) ssT += red[0][w2];
    float nrm = sqrtf(ssT);
    float inv = 1.f / fmaxf(nrm, 1e-12f);

    size_t base = ((size_t)hh * S + s) * FF;
    split_write(m0 * inv, outh, outl, base + t);
    split_write(m1 * inv, outh, outl, base + 256 + t);
    split_write(m2 * inv, outh, outl, base + 512 + t);

    if (WITHDEN && t < 4) {
        float dT = 0.f;
#pragma unroll
        for (int w2 = 0; w2 < 8; w2++) dT += red[1 + t][w2];
        float den  = dT * inv + EPSV;
        float mksq = ssT * inv * inv;
        float coef = 1.f - den / mksq;
        coef = fminf(fmaxf(coef, 0.f), 1.f);
        int h = 4 * hh + t;
        g_DEN[h * S + s]  = den;
        g_COEF[h * S + s] = coef;
    }
}

// weighted_mv = (v - num/denom) * mb -> bf16 hi/lo
__global__ void wmv_kernel()
{
    size_t idx = (size_t)blockIdx.x * 256 + threadIdx.x;
    int h = (int)(idx >> 19);
    size_t r = idx & ((1u << 19) - 1);
    int s  = (int)(r >> 7);
    int d0 = (int)(r & 127);
    float den  = g_DEN[h * S + s];
    float prev = g_NUM[idx] / den;
    float v  = g_V[(size_t)s * 512 + (size_t)(h >> 2) * 128 + d0];
    float mb = g_MB[(size_t)s * HID + (size_t)h * 128 + d0];
    split_write((v - prev) * mb, g_WMVH, g_WMVL, idx);
}

// new_norm[h][f] = norm[h][f] + sum_s coef[h][s]*MK[h/4][s][f]   (MK = hi+lo)
__global__ __launch_bounds__(256) void delta_norm_kernel(
    const float* __restrict__ normv, float* __restrict__ out_norm)
{
    const int kv = blockIdx.y;
    const int f0 = blockIdx.x * 64;
    const int t  = threadIdx.x;
    const int fl = t & 63, sl = t >> 6;

    float acc[4] = {0.f, 0.f, 0.f, 0.f};
    const __nv_bfloat16* mh = g_MKH + (size_t)kv * S * FF + f0 + fl;
    const __nv_bfloat16* ml = g_MKL + (size_t)kv * S * FF + f0 + fl;
    for (int s = sl; s < S; s += 4) {
        float v = __bfloat162float(mh[(size_t)s * FF]) + __bfloat162float(ml[(size_t)s * FF]);
#pragma unroll
        for (int g = 0; g < 4; g++)
            acc[g] = fmaf(g_COEF[(4 * kv + g) * S + s], v, acc[g]);
    }
    __shared__ float smr[4][4][64];
#pragma unroll
    for (int g = 0; g < 4; g++) smr[sl][g][fl] = acc[g];
    __syncthreads();
    if (t < 64) {
#pragma unroll
        for (int g = 0; g < 4; g++) {
            float sum = smr[0][g][t] + smr[1][g][t] + smr[2][g][t] + smr[3][g][t];
            int h = 4 * kv + g;
            out_norm[(size_t)h * FF + f0 + t] = normv[(size_t)h * FF + f0 + t] + sum;
        }
    }
}

// new_memory = memory + sum partials; also emit hi/lo bf16
__global__ void add_delta_kernel(const float* __restrict__ memory,
                                 float* __restrict__ out_mem)
{
    size_t idx = (size_t)blockIdx.x * 256 + threadIdx.x;
    float v = memory[idx] + g_DELTA[0][idx] + g_DELTA[1][idx]
            + g_DELTA[2][idx] + g_DELTA[3][idx];
    out_mem[idx] = v;
    split_write(v, g_NMemH, g_NMemL, idx);
}

__global__ void final_kernel(const float* __restrict__ X, float* __restrict__ out)
{
    size_t idx = (size_t)blockIdx.x * 256 + threadIdx.x;
    int s  = (int)(idx >> 11);
    int c  = (int)(idx & 2047);
    int h  = c >> 7;
    int d0 = c & 127;
    float numa = g_NUM[((size_t)h * S + s) * DD + d0];
    float mh = numa / g_DENA[h * S + s];
    out[idx] = X[idx] + g_G[idx] * mh;
}

// ======================================================================
// Launch
// ======================================================================
extern "C" void kernel_launch(void* const* d_in, const int* in_sizes, int n_in,
                              void* d_out, int out_size)
{
    const float* X    = (const float*)d_in[0];
    const float* Wq   = (const float*)d_in[1];
    const float* bq   = (const float*)d_in[2];
    const float* Wk   = (const float*)d_in[3];
    const float* bk   = (const float*)d_in[4];
    const float* Wv   = (const float*)d_in[5];
    const float* bv   = (const float*)d_in[6];
    const float* Wg   = (const float*)d_in[7];
    const float* bg   = (const float*)d_in[8];
    const float* Wmb  = (const float*)d_in[9];
    const float* bmb  = (const float*)d_in[10];
    const float* memv = (const float*)d_in[11];
    const float* normv= (const float*)d_in[12];

    float* out      = (float*)d_out;
    float* out_mem  = out + OUT_ELEMS;
    float* out_norm = out_mem + MEM_ELEMS;

    float *pK, *pV, *pQ, *pMB, *pG, *pNUM;
    cudaGetSymbolAddress((void**)&pK,  g_K);
    cudaGetSymbolAddress((void**)&pV,  g_V);
    cudaGetSymbolAddress((void**)&pQ,  g_Q);
    cudaGetSymbolAddress((void**)&pMB, g_MB);
    cudaGetSymbolAddress((void**)&pG,  g_G);
    cudaGetSymbolAddress((void**)&pNUM, g_NUM);

    __nv_bfloat16 *xh, *xl, *wqh, *wql, *wmh, *wml, *wgh, *wgl, *wkh, *wkl, *wvh, *wvl;
    __nv_bfloat16 *mkh, *mkl, *mqh, *mql, *memh, *meml, *nmh, *nml;
    cudaGetSymbolAddress((void**)&xh,  g_XH);  cudaGetSymbolAddress((void**)&xl,  g_XL);
    cudaGetSymbolAddress((void**)&wqh, g_WqH); cudaGetSymbolAddress((void**)&wql, g_WqL);
    cudaGetSymbolAddress((void**)&wmh, g_WmH); cudaGetSymbolAddress((void**)&wml, g_WmL);
    cudaGetSymbolAddress((void**)&wgh, g_WgH); cudaGetSymbolAddress((void**)&wgl, g_WgL);
    cudaGetSymbolAddress((void**)&wkh, g_WkH); cudaGetSymbolAddress((void**)&wkl, g_WkL);
    cudaGetSymbolAddress((void**)&wvh, g_WvH); cudaGetSymbolAddress((void**)&wvl, g_WvL);
    cudaGetSymbolAddress((void**)&mkh, g_MKH); cudaGetSymbolAddress((void**)&mkl, g_MKL);
    cudaGetSymbolAddress((void**)&mqh, g_MQH); cudaGetSymbolAddress((void**)&mql, g_MQL);
    cudaGetSymbolAddress((void**)&memh, g_MemH); cudaGetSymbolAddress((void**)&meml, g_MemL);
    cudaGetSymbolAddress((void**)&nmh, g_NMemH); cudaGetSymbolAddress((void**)&nml, g_NMemL);

    cudaFuncSetAttribute(gemm_mma<0,256>, cudaFuncAttributeMaxDynamicSharedMemorySize, PJ_SMEM_256);
    cudaFuncSetAttribute(gemm_mma<1,256>, cudaFuncAttributeMaxDynamicSharedMemorySize, PJ_SMEM_256);
    cudaFuncSetAttribute(gemm_mma<0,128>, cudaFuncAttributeMaxDynamicSharedMemorySize, PJ_SMEM_128);
    cudaFuncSetAttribute(gemm_skinny_mma<0>, cudaFuncAttributeMaxDynamicSharedMemorySize, SK_SMEM);
    cudaFuncSetAttribute(gemm_skinny_mma<1>, cudaFuncAttributeMaxDynamicSharedMemorySize, SK_SMEM);
    cudaFuncSetAttribute(gemm_delta_mma, cudaFuncAttributeMaxDynamicSharedMemorySize, DL_SMEM);

    dim3 blk(256);

    // 0) fp32 -> bf16 hi/lo splits
    cvt_split<<<(S * HID / 4 + 255) / 256, blk>>>(X,   xh,  xl,  S * HID / 4);
    cvt_split<<<(HID * HID / 4 + 255) / 256, blk>>>(Wq,  wqh, wql, HID * HID / 4);
    cvt_split<<<(HID * HID / 4 + 255) / 256, blk>>>(Wmb, wmh, wml, HID * HID / 4);
    cvt_split<<<(HID * HID / 4 + 255) / 256, blk>>>(Wg,  wgh, wgl, HID * HID / 4);
    cvt_split<<<(512 * HID / 4 + 255) / 256, blk>>>(Wk,  wkh, wkl, 512 * HID / 4);
    cvt_split<<<(512 * HID / 4 + 255) / 256, blk>>>(Wv,  wvh, wvl, 512 * HID / 4);
    cvt_split<<<(MEM_ELEMS / 4 + 255) / 256, blk>>>(memv, memh, meml, MEM_ELEMS / 4);

    // 1) Projections on tensor cores (big: 128x256 tiles; K/V: 128x128)
    gemm_mma<0,256><<<dim3(HID / 256, S / 128), blk, PJ_SMEM_256>>>(xh, xl, wqh, wql, bq,  pQ,  HID, HID);
    gemm_mma<0,128><<<dim3(512 / 128, S / 128), blk, PJ_SMEM_128>>>(xh, xl, wkh, wkl, bk,  pK,  512, HID);
    gemm_mma<0,128><<<dim3(512 / 128, S / 128), blk, PJ_SMEM_128>>>(xh, xl, wvh, wvl, bv,  pV,  512, HID);
    gemm_mma<1,256><<<dim3(HID / 256, S / 128), blk, PJ_SMEM_256>>>(xh, xl, wmh, wml, bmb, pMB, HID, HID);
    gemm_mma<1,256><<<dim3(HID / 256, S / 128), blk, PJ_SMEM_256>>>(xh, xl, wgh, wgl, bg,  pG,  HID, HID);

    // 2) dpfp + normalize (bf16 hi/lo outputs)
    dpfp_kernel<true ><<<dim3(S, NKV), blk>>>(pK, mkh, mkl, normv);
    dpfp_kernel<false><<<dim3(S, NH ), blk>>>(pQ, mqh, mql, nullptr);

    // 3) num = ext_mk @ memory (tensor cores)
    gemm_skinny_mma<0><<<dim3(S / 128, NH), blk, SK_SMEM>>>(mkh, mkl, 4, memh, meml, pNUM, nullptr);

    // 4) weighted_mv (bf16 hi/lo out)
    wmv_kernel<<<(NH * S * DD) / 256, blk>>>();

    // 5) delta_memory (tensor cores, split-K=4), delta_norm, add
    gemm_delta_mma<<<dim3(FF / 128, 4, NH), blk, DL_SMEM>>>();
    delta_norm_kernel<<<dim3(FF / 64, NKV), blk>>>(normv, out_norm);
    add_delta_kernel<<<MEM_ELEMS / 256, blk>>>(memv, out_mem);

    // 6) associate: num_a GEMM with fused den_a, then output
    gemm_skinny_mma<1><<<dim3(S / 128, NH), blk, SK_SMEM>>>(mqh, mql, 1, nmh, nml, pNUM, out_norm);
    final_kernel<<<OUT_ELEMS / 256, blk>>>(X, out);
}

// round 13
// speedup vs baseline: 1.0048x; 1.0048x over previous
#include <cuda_runtime.h>
#include <cuda_bf16.h>
#include <math.h>
#include <stdint.h>

// ---------------- Problem constants ----------------
#define S      4096
#define HID    2048
#define NH     16
#define NKV    4
#define DD     128
#define FF     768
#define EPSV   1e-8f

#define OUT_ELEMS    (S * HID)
#define MEM_ELEMS    (NH * FF * DD)

// ---------------- Scratch (device globals; no allocation allowed) ----------------
__device__ __align__(16) float g_K  [S * 512];
__device__ __align__(16) float g_V  [S * 512];
__device__ __align__(16) float g_Q  [S * HID];
__device__ __align__(16) float g_MB [S * HID];
__device__ __align__(16) float g_G  [S * HID];
__device__ __align__(16) float g_NUM[(size_t)NH * S * DD];
__device__ __align__(16) float g_DELTA[4][(size_t)NH * FF * DD];
__device__ float g_DEN [NH * S];
__device__ float g_COEF[NH * S];
__device__ float g_DENA[NH * S];

// bf16 split operands
__device__ __align__(16) __nv_bfloat16 g_XH [S * HID];
__device__ __align__(16) __nv_bfloat16 g_XL [S * HID];
__device__ __align__(16) __nv_bfloat16 g_WqH[HID * HID], g_WqL[HID * HID];
__device__ __align__(16) __nv_bfloat16 g_WmH[HID * HID], g_WmL[HID * HID];
__device__ __align__(16) __nv_bfloat16 g_WgH[HID * HID], g_WgL[HID * HID];
__device__ __align__(16) __nv_bfloat16 g_WkH[512 * HID], g_WkL[512 * HID];
__device__ __align__(16) __nv_bfloat16 g_WvH[512 * HID], g_WvL[512 * HID];
__device__ __align__(16) __nv_bfloat16 g_MKH[(size_t)NKV * S * FF], g_MKL[(size_t)NKV * S * FF];
__device__ __align__(16) __nv_bfloat16 g_MQH[(size_t)NH * S * FF], g_MQL[(size_t)NH * S * FF];
__device__ __align__(16) __nv_bfloat16 g_MemH[MEM_ELEMS],  g_MemL[MEM_ELEMS];
__device__ __align__(16) __nv_bfloat16 g_NMemH[MEM_ELEMS], g_NMemL[MEM_ELEMS];
__device__ __align__(16) __nv_bfloat16 g_WMVH[(size_t)NH * S * DD], g_WMVL[(size_t)NH * S * DD];

// ---------------- helpers ----------------
__device__ __forceinline__ float warp_sum(float v) {
#pragma unroll
    for (int o = 16; o > 0; o >>= 1) v += __shfl_down_sync(0xffffffffu, v, o);
    return v;
}
__device__ __forceinline__ uint32_t smem_u32(const void* p) {
    uint32_t a;
    asm("{ .reg .u64 t; cvta.to.shared.u64 t, %1; cvt.u32.u64 %0, t; }"
        : "=r"(a) : "l"(p));
    return a;
}
__device__ __forceinline__ void cp_async16(uint32_t sa, const void* g) {
    asm volatile("cp.async.cg.shared.global [%0], [%1], 16;" :: "r"(sa), "l"(g) : "memory");
}
__device__ __forceinline__ void cp_commit() {
    asm volatile("cp.async.commit_group;" ::: "memory");
}
template<int N> __device__ __forceinline__ void cp_wait() {
    asm volatile("cp.async.wait_group %0;" :: "n"(N) : "memory");
}
__device__ __forceinline__ void ldm_x4(uint32_t* r, uint32_t addr) {
    asm volatile("ldmatrix.sync.aligned.m8n8.x4.shared.b16 {%0,%1,%2,%3}, [%4];"
                 : "=r"(r[0]), "=r"(r[1]), "=r"(r[2]), "=r"(r[3]) : "r"(addr));
}
__device__ __forceinline__ void ldm_x2(uint32_t* r, uint32_t addr) {
    asm volatile("ldmatrix.sync.aligned.m8n8.x2.shared.b16 {%0,%1}, [%2];"
                 : "=r"(r[0]), "=r"(r[1]) : "r"(addr));
}
__device__ __forceinline__ void ldm_x4_t(uint32_t* r, uint32_t addr) {
    asm volatile("ldmatrix.sync.aligned.m8n8.x4.trans.shared.b16 {%0,%1,%2,%3}, [%4];"
                 : "=r"(r[0]), "=r"(r[1]), "=r"(r[2]), "=r"(r[3]) : "r"(addr));
}
__device__ __forceinline__ void ldm_x2_t(uint32_t* r, uint32_t addr) {
    asm volatile("ldmatrix.sync.aligned.m8n8.x2.trans.shared.b16 {%0,%1}, [%2];"
                 : "=r"(r[0]), "=r"(r[1]) : "r"(addr));
}
__device__ __forceinline__ void mma_bf16(float* c, const uint32_t* a, const uint32_t* b) {
    asm volatile(
        "mma.sync.aligned.m16n8k16.row.col.f32.bf16.bf16.f32 "
        "{%0,%1,%2,%3}, {%4,%5,%6,%7}, {%8,%9}, {%0,%1,%2,%3};"
        : "+f"(c[0]), "+f"(c[1]), "+f"(c[2]), "+f"(c[3])
        : "r"(a[0]), "r"(a[1]), "r"(a[2]), "r"(a[3]), "r"(b[0]), "r"(b[1]));
}
__device__ __forceinline__ void split_write(float v, __nv_bfloat16* hp, __nv_bfloat16* lp,
                                            size_t idx) {
    __nv_bfloat16 h = __float2bfloat16(v);
    hp[idx] = h;
    lp[idx] = __float2bfloat16(v - __bfloat162float(h));
}

// ======================================================================
// fp32 -> bf16 hi/lo split conversion (vectorized x4)
// ======================================================================
__global__ void cvt_split(const float* __restrict__ x,
                          __nv_bfloat16* __restrict__ hi,
                          __nv_bfloat16* __restrict__ lo, int n4)
{
    int i = blockIdx.x * 256 + threadIdx.x;
    if (i >= n4) return;
    float4 v = ((const float4*)x)[i];
    __nv_bfloat16 h0 = __float2bfloat16(v.x), h1 = __float2bfloat16(v.y);
    __nv_bfloat16 h2 = __float2bfloat16(v.z), h3 = __float2bfloat16(v.w);
    __nv_bfloat16 l0 = __float2bfloat16(v.x - __bfloat162float(h0));
    __nv_bfloat16 l1 = __float2bfloat16(v.y - __bfloat162float(h1));
    __nv_bfloat16 l2 = __float2bfloat16(v.z - __bfloat162float(h2));
    __nv_bfloat16 l3 = __float2bfloat16(v.w - __bfloat162float(h3));
    __nv_bfloat162* hp = (__nv_bfloat162*)hi;
    __nv_bfloat162* lp = (__nv_bfloat162*)lo;
    hp[2 * i]     = __nv_bfloat162(h0, h1);
    hp[2 * i + 1] = __nv_bfloat162(h2, h3);
    lp[2 * i]     = __nv_bfloat162(l0, l1);
    lp[2 * i + 1] = __nv_bfloat162(l2, l3);
}

// ======================================================================
// Projection GEMM (bf16-split mma.sync): C = A @ W^T + bias (opt sigmoid)
// BM=128, BN template (128 or 256), BK=32, 256 threads, 8 warps (2 x 4),
// warp tile 64 x (BN/4). 3-stage cp.async pipeline, one barrier/chunk.
// ======================================================================
#define PJ_A_T 10240                        // 128 rows * 80B

template <int ACT, int BN>
__global__ __launch_bounds__(256, 1) void gemm_mma(
    const __nv_bfloat16* __restrict__ Ahi, const __nv_bfloat16* __restrict__ Alo,
    const __nv_bfloat16* __restrict__ Bhi, const __nv_bfloat16* __restrict__ Blo,
    const float* __restrict__ bias, float* __restrict__ C, int N, int K)
{
    extern __shared__ char sm[];
    constexpr int NT   = BN / 32;           // nt iterations per warp
    constexpr int B_T  = BN * 80;           // B tile bytes per half
    constexpr int STG  = 2 * PJ_A_T + 2 * B_T;
    const int tid  = threadIdx.x;
    const int lane = tid & 31;
    const int warp = tid >> 5;
    const int wm = warp >> 2;
    const int wn = warp & 3;
    const int bm = blockIdx.y * 128;
    const int bn = blockIdx.x * BN;
    const uint32_t sbase = smem_u32(sm);

    auto load_chunk = [&](int c, int st) {
        const int k0 = c << 5;
        const uint32_t stb = sbase + (uint32_t)st * STG;
#pragma unroll
        for (int half = 0; half < 2; ++half) {
            const __nv_bfloat16* src = (half ? Alo : Ahi) + (size_t)bm * K + k0;
#pragma unroll
            for (int rep = 0; rep < 2; ++rep) {
                int i = tid + rep * 256;
                int r = i >> 2, cc = i & 3;
                cp_async16(stb + (uint32_t)half * PJ_A_T + r * 80 + cc * 16,
                           src + (size_t)r * K + cc * 8);
            }
        }
#pragma unroll
        for (int half = 0; half < 2; ++half) {
            const __nv_bfloat16* src = (half ? Blo : Bhi) + (size_t)bn * K + k0;
#pragma unroll
            for (int rep = 0; rep < BN / 64; ++rep) {
                int i = tid + rep * 256;
                int r = i >> 2, cc = i & 3;
                cp_async16(stb + 2 * PJ_A_T + (uint32_t)half * B_T + r * 80 + cc * 16,
                           src + (size_t)r * K + cc * 8);
            }
        }
        cp_commit();
    };

    float acc[4][NT][4];
#pragma unroll
    for (int mt = 0; mt < 4; ++mt)
#pragma unroll
        for (int nt = 0; nt < NT; ++nt)
#pragma unroll
            for (int r = 0; r < 4; ++r) acc[mt][nt][r] = 0.f;

    const int NC = K >> 5;
    load_chunk(0, 0);
    load_chunk(1, 1);

    for (int c = 0; c < NC; ++c) {
        if (c + 1 < NC) cp_wait<1>(); else cp_wait<0>();
        __syncthreads();
        if (c + 2 < NC) load_chunk(c + 2, (c + 2) % 3);

        const uint32_t stb = sbase + (uint32_t)(c % 3) * STG;
#pragma unroll
        for (int k16 = 0; k16 < 2; ++k16) {
            uint32_t ah[4][4], al[4][4];
#pragma unroll
            for (int mt = 0; mt < 4; ++mt) {
                uint32_t rowa = (uint32_t)(wm * 64 + mt * 16 + (lane & 15));
                uint32_t coff = (uint32_t)((k16 * 16 + ((lane >> 4) << 3)) * 2);
                ldm_x4(ah[mt], stb + 0 * PJ_A_T + rowa * 80 + coff);
                ldm_x4(al[mt], stb + 1 * PJ_A_T + rowa * 80 + coff);
            }
#pragma unroll
            for (int nt = 0; nt < NT; ++nt) {
                uint32_t rowb = (uint32_t)(wn * (BN / 4) + nt * 8 + (lane & 7));
                uint32_t coff = (uint32_t)((k16 * 16 + (((lane >> 3) & 1) << 3)) * 2);
                uint32_t bh[2], bl[2];
                ldm_x2(bh, stb + 2 * PJ_A_T + 0 * B_T + rowb * 80 + coff);
                ldm_x2(bl, stb + 2 * PJ_A_T + 1 * B_T + rowb * 80 + coff);
#pragma unroll
                for (int mt = 0; mt < 4; ++mt) {
                    mma_bf16(acc[mt][nt], ah[mt], bh);
                    mma_bf16(acc[mt][nt], ah[mt], bl);
                    mma_bf16(acc[mt][nt], al[mt], bh);
                }
            }
        }
    }

    const int r0 = bm + wm * 64;
    const int c0 = bn + wn * (BN / 4);
    const int rl = lane >> 2;
    const int cl = (lane & 3) * 2;
#pragma unroll
    for (int mt = 0; mt < 4; ++mt) {
#pragma unroll
        for (int nt = 0; nt < NT; ++nt) {
            int col = c0 + nt * 8 + cl;
            float b0 = bias[col], b1 = bias[col + 1];
#pragma unroll
            for (int half = 0; half < 2; ++half) {
                int row = r0 + mt * 16 + rl + half * 8;
                float v0 = acc[mt][nt][2 * half + 0] + b0;
                float v1 = acc[mt][nt][2 * half + 1] + b1;
                if (ACT) {
                    v0 = 1.f / (1.f + expf(-v0));
                    v1 = 1.f / (1.f + expf(-v1));
                }
                *(float2*)(C + (size_t)row * N + col) = make_float2(v0, v1);
            }
        }
    }
}

#define PJ_SMEM_128 (3 * (2 * PJ_A_T + 2 * 128 * 80))   // 122880
#define PJ_SMEM_256 (3 * (2 * PJ_A_T + 2 * 256 * 80))   // 184320

// ======================================================================
// Skinny einsum GEMM (bf16-split): per head h,
// C[h][tile,128] = A[h/adiv][M,768] @ B[h][768,128].
// 3-stage pipeline. WITHDEN: fuse den_a[s] = dot(mq[s,:], nrm[h,:]) + EPS.
// ======================================================================
#define SK_AT_B 10240                 // A tile: 128 x 80B
#define SK_BT_B 8704                  // B tile: 32 x 272B
#define SK_STAGE (2*SK_AT_B + 2*SK_BT_B)   // 37888
#define SK_SMEM  (3 * SK_STAGE)            // 113664

template <int WITHDEN>
__global__ __launch_bounds__(256, 1) void gemm_skinny_mma(
    const __nv_bfloat16* __restrict__ AH, const __nv_bfloat16* __restrict__ AL,
    int adiv,
    const __nv_bfloat16* __restrict__ BH, const __nv_bfloat16* __restrict__ BL,
    float* __restrict__ Cbase, const float* __restrict__ nrm)
{
    extern __shared__ char sm[];
    const int tid  = threadIdx.x;
    const int lane = tid & 31;
    const int warp = tid >> 5;
    const int wm = warp >> 2;
    const int wn = warp & 3;
    const int h  = blockIdx.y;
    const int bm = blockIdx.x * 128;
    const uint32_t sbase = smem_u32(sm);

    const __nv_bfloat16* Ah = AH + (size_t)(h / adiv) * S * FF;
    const __nv_bfloat16* Al = AL + (size_t)(h / adiv) * S * FF;
    const __nv_bfloat16* Bh = BH + (size_t)h * FF * DD;
    const __nv_bfloat16* Bl = BL + (size_t)h * FF * DD;
    float* C = Cbase + (size_t)h * S * DD;

    auto load_chunk = [&](int c, int st) {
        const int k0 = c << 5;
        const uint32_t stb = sbase + (uint32_t)st * SK_STAGE;
        const __nv_bfloat16* asrc[2] = {Ah, Al};
        const __nv_bfloat16* bsrc[2] = {Bh, Bl};
#pragma unroll
        for (int half = 0; half < 2; ++half) {
#pragma unroll
            for (int rep = 0; rep < 2; ++rep) {
                int i = tid + rep * 256;
                int r = i >> 2, cc = i & 3;
                cp_async16(stb + (uint32_t)half * SK_AT_B + r * 80 + cc * 16,
                           asrc[half] + (size_t)(bm + r) * FF + k0 + cc * 8);
            }
#pragma unroll
            for (int rep = 0; rep < 2; ++rep) {
                int i = tid + rep * 256;
                int r = i >> 4, cc = i & 15;
                cp_async16(stb + 2 * SK_AT_B + (uint32_t)half * SK_BT_B + r * 272 + cc * 16,
                           bsrc[half] + (size_t)(k0 + r) * DD + cc * 8);
            }
        }
        cp_commit();
    };

    float acc[4][4][4];
#pragma unroll
    for (int mt = 0; mt < 4; ++mt)
#pragma unroll
        for (int nt = 0; nt < 4; ++nt)
#pragma unroll
            for (int r = 0; r < 4; ++r) acc[mt][nt][r] = 0.f;

    float den = 0.f;
    const float* nrh = WITHDEN ? (nrm + (size_t)h * FF) : nullptr;

    const int NC = FF >> 5;   // 24
    load_chunk(0, 0);
    load_chunk(1, 1);

    for (int c = 0; c < NC; ++c) {
        if (c + 1 < NC) cp_wait<1>(); else cp_wait<0>();
        __syncthreads();
        if (c + 2 < NC) load_chunk(c + 2, (c + 2) % 3);

        const int st = c % 3;
        const uint32_t stb = sbase + (uint32_t)st * SK_STAGE;

        if (WITHDEN) {
            // den partial: 2 threads per row, 16 cols each, from A smem tiles
            int r = tid >> 1, cs = (tid & 1) * 16;
            const __nv_bfloat16* ph =
                (const __nv_bfloat16*)(sm + (size_t)st * SK_STAGE + (size_t)r * 80);
            const __nv_bfloat16* pl =
                (const __nv_bfloat16*)(sm + (size_t)st * SK_STAGE + SK_AT_B + (size_t)r * 80);
            const float* nr = nrh + (c << 5) + cs;
#pragma unroll
            for (int j = 0; j < 16; ++j) {
                float v = __bfloat162float(ph[cs + j]) + __bfloat162float(pl[cs + j]);
                den = fmaf(v, nr[j], den);
            }
        }

#pragma unroll
        for (int k16 = 0; k16 < 2; ++k16) {
            uint32_t ah[4][4], al[4][4];
#pragma unroll
            for (int mt = 0; mt < 4; ++mt) {
                uint32_t rowa = (uint32_t)(wm * 64 + mt * 16 + (lane & 15));
                uint32_t coff = (uint32_t)((k16 * 16 + ((lane >> 4) << 3)) * 2);
                ldm_x4(ah[mt], stb + 0 * SK_AT_B + rowa * 80 + coff);
                ldm_x4(al[mt], stb + 1 * SK_AT_B + rowa * 80 + coff);
            }
#pragma unroll
            for (int nt = 0; nt < 4; ++nt) {
                uint32_t rowb = (uint32_t)(k16 * 16 + (lane & 15));
                uint32_t noff = (uint32_t)((wn * 32 + nt * 8) * 2);
                uint32_t bh[2], bl[2];
                ldm_x2_t(bh, stb + 2 * SK_AT_B + 0 * SK_BT_B + rowb * 272 + noff);
                ldm_x2_t(bl, stb + 2 * SK_AT_B + 1 * SK_BT_B + rowb * 272 + noff);
#pragma unroll
                for (int mt = 0; mt < 4; ++mt) {
                    mma_bf16(acc[mt][nt], ah[mt], bh);
                    mma_bf16(acc[mt][nt], ah[mt], bl);
                    mma_bf16(acc[mt][nt], al[mt], bh);
                }
            }
        }
    }

    if (WITHDEN) {
        den += __shfl_xor_sync(0xffffffffu, den, 1);
        if (!(tid & 1))
            g_DENA[(size_t)h * S + bm + (tid >> 1)] = den + EPSV;
    }

    const int r0 = bm + wm * 64;
    const int c0 = wn * 32;
    const int rl = lane >> 2;
    const int cl = (lane & 3) * 2;
#pragma unroll
    for (int mt = 0; mt < 4; ++mt)
#pragma unroll
        for (int nt = 0; nt < 4; ++nt) {
            int col = c0 + nt * 8 + cl;
#pragma unroll
            for (int half = 0; half < 2; ++half) {
                int row = r0 + mt * 16 + rl + half * 8;
                *(float2*)(C + (size_t)row * DD + col) =
                    make_float2(acc[mt][nt][2 * half], acc[mt][nt][2 * half + 1]);
            }
        }
}

// ======================================================================
// Delta GEMM (bf16-split, split-K=4), 3-stage pipeline:
// DELTA[part][h][f,d] = sum_{s in part} MK[h/4][s,f] * WMV[h][s,d]
// ======================================================================
#define DL_T_B 8704                   // 32 x 272B
#define DL_STAGE (4 * DL_T_B)         // 34816
#define DL_SMEM  (3 * DL_STAGE)       // 104448

__global__ __launch_bounds__(256, 1) void gemm_delta_mma()
{
    extern __shared__ char sm[];
    const int tid  = threadIdx.x;
    const int lane = tid & 31;
    const int warp = tid >> 5;
    const int wm = warp >> 2;
    const int wn = warp & 3;
    const int h    = blockIdx.z;
    const int part = blockIdx.y;
    const int f0   = blockIdx.x * 128;
    const uint32_t sbase = smem_u32(sm);

    const __nv_bfloat16* Ah = g_MKH + (size_t)(h >> 2) * S * FF;
    const __nv_bfloat16* Al = g_MKL + (size_t)(h >> 2) * S * FF;
    const __nv_bfloat16* Bh = g_WMVH + (size_t)h * S * DD;
    const __nv_bfloat16* Bl = g_WMVL + (size_t)h * S * DD;

    const int kbase = part * (S / 4);

    auto load_chunk = [&](int c, int st) {
        const int k0 = kbase + (c << 5);
        const uint32_t stb = sbase + (uint32_t)st * DL_STAGE;
        const __nv_bfloat16* srcs[4] = {Ah, Al, Bh, Bl};
#pragma unroll
        for (int tile = 0; tile < 4; ++tile) {
            const bool isA = tile < 2;
#pragma unroll
            for (int rep = 0; rep < 2; ++rep) {
                int i = tid + rep * 256;
                int r = i >> 4, cc = i & 15;
                const __nv_bfloat16* src = isA
                    ? srcs[tile] + (size_t)(k0 + r) * FF + f0 + cc * 8
                    : srcs[tile] + (size_t)(k0 + r) * DD + cc * 8;
                cp_async16(stb + (uint32_t)tile * DL_T_B + r * 272 + cc * 16, src);
            }
        }
        cp_commit();
    };

    float acc[4][4][4];
#pragma unroll
    for (int mt = 0; mt < 4; ++mt)
#pragma unroll
        for (int nt = 0; nt < 4; ++nt)
#pragma unroll
            for (int r = 0; r < 4; ++r) acc[mt][nt][r] = 0.f;

    const int NC = (S / 4) >> 5;   // 32
    load_chunk(0, 0);
    load_chunk(1, 1);

    for (int c = 0; c < NC; ++c) {
        if (c + 1 < NC) cp_wait<1>(); else cp_wait<0>();
        __syncthreads();
        if (c + 2 < NC) load_chunk(c + 2, (c + 2) % 3);

        const uint32_t stb = sbase + (uint32_t)(c % 3) * DL_STAGE;
#pragma unroll
        for (int k16 = 0; k16 < 2; ++k16) {
            uint32_t ah[4][4], al[4][4];
            uint32_t rowa = (uint32_t)(k16 * 16 + (lane & 7) + ((lane >> 4) << 3));
#pragma unroll
            for (int mt = 0; mt < 4; ++mt) {
                uint32_t cola = (uint32_t)((wm * 64 + mt * 16 + (((lane >> 3) & 1) << 3)) * 2);
                ldm_x4_t(ah[mt], stb + 0 * DL_T_B + rowa * 272 + cola);
                ldm_x4_t(al[mt], stb + 1 * DL_T_B + rowa * 272 + cola);
            }
#pragma unroll
            for (int nt = 0; nt < 4; ++nt) {
                uint32_t rowb = (uint32_t)(k16 * 16 + (lane & 15));
                uint32_t noff = (uint32_t)((wn * 32 + nt * 8) * 2);
                uint32_t bh[2], bl[2];
                ldm_x2_t(bh, stb + 2 * DL_T_B + rowb * 272 + noff);
                ldm_x2_t(bl, stb + 3 * DL_T_B + rowb * 272 + noff);
#pragma unroll
                for (int mt = 0; mt < 4; ++mt) {
                    mma_bf16(acc[mt][nt], ah[mt], bh);
                    mma_bf16(acc[mt][nt], ah[mt], bl);
                    mma_bf16(acc[mt][nt], al[mt], bh);
                }
            }
        }
    }

    float* Cp = g_DELTA[part] + (size_t)h * FF * DD;
    const int r0 = f0 + wm * 64;
    const int c0 = wn * 32;
    const int rl = lane >> 2;
    const int cl = (lane & 3) * 2;
#pragma unroll
    for (int mt = 0; mt < 4; ++mt)
#pragma unroll
        for (int nt = 0; nt < 4; ++nt) {
            int col = c0 + nt * 8 + cl;
#pragma unroll
            for (int half = 0; half < 2; ++half) {
                int row = r0 + mt * 16 + rl + half * 8;
                *(float2*)(Cp + (size_t)row * DD + col) =
                    make_float2(acc[mt][nt][2 * half], acc[mt][nt][2 * half + 1]);
            }
        }
}

// ======================================================================
// dpfp + L2-normalize, emits bf16 hi/lo. K variant fuses denom/coef.
// ======================================================================
template <bool WITHDEN>
__global__ __launch_bounds__(256) void dpfp_kernel(
    const float* __restrict__ X,
    __nv_bfloat16* __restrict__ outh, __nv_bfloat16* __restrict__ outl,
    const float* __restrict__ normv)
{
    const int s  = blockIdx.x;
    const int hh = blockIdx.y;
    const int nh = gridDim.y;
    const int t  = threadIdx.x;
    __shared__ float y[256];
    __shared__ float red[5][8];

    const float* x = X + ((size_t)s * nh + hh) * 128;
    float xv = (t < 128) ? x[t] : -x[t - 128];
    y[t] = fmaxf(xv, 0.f);
    __syncthreads();

    float yi = y[t];
    float m0 = yi * y[(t - 1) & 255];
    float m1 = yi * y[(t - 2) & 255];
    float m2 = yi * y[(t - 3) & 255];
    float ss = m0 * m0 + m1 * m1 + m2 * m2;

    float dd[4];
    if (WITHDEN) {
#pragma unroll
        for (int g = 0; g < 4; g++) {
            const float* nr = normv + (size_t)(4 * hh + g) * FF;
            dd[g] = m0 * nr[t] + m1 * nr[256 + t] + m2 * nr[512 + t];
        }
    }

    const int lane = t & 31, w = t >> 5;
    float r0 = warp_sum(ss);
    if (lane == 0) red[0][w] = r0;
    if (WITHDEN) {
#pragma unroll
        for (int g = 0; g < 4; g++) {
            float rg = warp_sum(dd[g]);
            if (lane == 0) red[1 + g][w] = rg;
        }
    }
    __syncthreads();

    float ssT = 0.f;
#pragma unroll
    for (int w2 = 0; w2 < 8; w2++) ssT += red[0][w2];
    float nrm = sqrtf(ssT);
    float inv = 1.f / fmaxf(nrm, 1e-12f);

    size_t base = ((size_t)hh * S + s) * FF;
    split_write(m0 * inv, outh, outl, base + t);
    split_write(m1 * inv, outh, outl, base + 256 + t);
    split_write(m2 * inv, outh, outl, base + 512 + t);

    if (WITHDEN && t < 4) {
        float dT = 0.f;
#pragma unroll
        for (int w2 = 0; w2 < 8; w2++) dT += red[1 + t][w2];
        float den  = dT * inv + EPSV;
        float mksq = ssT * inv * inv;
        float coef = 1.f - den / mksq;
        coef = fminf(fmaxf(coef, 0.f), 1.f);
        int h = 4 * hh + t;
        g_DEN[h * S + s]  = den;
        g_COEF[h * S + s] = coef;
    }
}

// weighted_mv = (v - num/denom) * mb -> bf16 hi/lo
__global__ void wmv_kernel()
{
    size_t idx = (size_t)blockIdx.x * 256 + threadIdx.x;
    int h = (int)(idx >> 19);
    size_t r = idx & ((1u << 19) - 1);
    int s  = (int)(r >> 7);
    int d0 = (int)(r & 127);
    float den  = g_DEN[h * S + s];
    float prev = g_NUM[idx] / den;
    float v  = g_V[(size_t)s * 512 + (size_t)(h >> 2) * 128 + d0];
    float mb = g_MB[(size_t)s * HID + (size_t)h * 128 + d0];
    split_write((v - prev) * mb, g_WMVH, g_WMVL, idx);
}

// new_norm[h][f] = norm[h][f] + sum_s coef[h][s]*MK[h/4][s][f]   (MK = hi+lo)
__global__ __launch_bounds__(256) void delta_norm_kernel(
    const float* __restrict__ normv, float* __restrict__ out_norm)
{
    const int kv = blockIdx.y;
    const int f0 = blockIdx.x * 64;
    const int t  = threadIdx.x;
    const int fl = t & 63, sl = t >> 6;

    float acc[4] = {0.f, 0.f, 0.f, 0.f};
    const __nv_bfloat16* mh = g_MKH + (size_t)kv * S * FF + f0 + fl;
    const __nv_bfloat16* ml = g_MKL + (size_t)kv * S * FF + f0 + fl;
    for (int s = sl; s < S; s += 4) {
        float v = __bfloat162float(mh[(size_t)s * FF]) + __bfloat162float(ml[(size_t)s * FF]);
#pragma unroll
        for (int g = 0; g < 4; g++)
            acc[g] = fmaf(g_COEF[(4 * kv + g) * S + s], v, acc[g]);
    }
    __shared__ float smr[4][4][64];
#pragma unroll
    for (int g = 0; g < 4; g++) smr[sl][g][fl] = acc[g];
    __syncthreads();
    if (t < 64) {
#pragma unroll
        for (int g = 0; g < 4; g++) {
            float sum = smr[0][g][t] + smr[1][g][t] + smr[2][g][t] + smr[3][g][t];
            int h = 4 * kv + g;
            out_norm[(size_t)h * FF + f0 + t] = normv[(size_t)h * FF + f0 + t] + sum;
        }
    }
}

// new_memory = memory + sum partials; also emit hi/lo bf16
__global__ void add_delta_kernel(const float* __restrict__ memory,
                                 float* __restrict__ out_mem)
{
    size_t idx = (size_t)blockIdx.x * 256 + threadIdx.x;
    float v = memory[idx] + g_DELTA[0][idx] + g_DELTA[1][idx]
            + g_DELTA[2][idx] + g_DELTA[3][idx];
    out_mem[idx] = v;
    split_write(v, g_NMemH, g_NMemL, idx);
}

__global__ void final_kernel(const float* __restrict__ X, float* __restrict__ out)
{
    size_t idx = (size_t)blockIdx.x * 256 + threadIdx.x;
    int s  = (int)(idx >> 11);
    int c  = (int)(idx & 2047);
    int h  = c >> 7;
    int d0 = c & 127;
    float numa = g_NUM[((size_t)h * S + s) * DD + d0];
    float mh = numa / g_DENA[h * S + s];
    out[idx] = X[idx] + g_G[idx] * mh;
}

// ======================================================================
// Launch
// ======================================================================
extern "C" void kernel_launch(void* const* d_in, const int* in_sizes, int n_in,
                              void* d_out, int out_size)
{
    const float* X    = (const float*)d_in[0];
    const float* Wq   = (const float*)d_in[1];
    const float* bq   = (const float*)d_in[2];
    const float* Wk   = (const float*)d_in[3];
    const float* bk   = (const float*)d_in[4];
    const float* Wv   = (const float*)d_in[5];
    const float* bv   = (const float*)d_in[6];
    const float* Wg   = (const float*)d_in[7];
    const float* bg   = (const float*)d_in[8];
    const float* Wmb  = (const float*)d_in[9];
    const float* bmb  = (const float*)d_in[10];
    const float* memv = (const float*)d_in[11];
    const float* normv= (const float*)d_in[12];

    float* out      = (float*)d_out;
    float* out_mem  = out + OUT_ELEMS;
    float* out_norm = out_mem + MEM_ELEMS;

    float *pK, *pV, *pQ, *pMB, *pG, *pNUM;
    cudaGetSymbolAddress((void**)&pK,  g_K);
    cudaGetSymbolAddress((void**)&pV,  g_V);
    cudaGetSymbolAddress((void**)&pQ,  g_Q);
    cudaGetSymbolAddress((void**)&pMB, g_MB);
    cudaGetSymbolAddress((void**)&pG,  g_G);
    cudaGetSymbolAddress((void**)&pNUM, g_NUM);

    __nv_bfloat16 *xh, *xl, *wqh, *wql, *wmh, *wml, *wgh, *wgl, *wkh, *wkl, *wvh, *wvl;
    __nv_bfloat16 *mkh, *mkl, *mqh, *mql, *memh, *meml, *nmh, *nml;
    cudaGetSymbolAddress((void**)&xh,  g_XH);  cudaGetSymbolAddress((void**)&xl,  g_XL);
    cudaGetSymbolAddress((void**)&wqh, g_WqH); cudaGetSymbolAddress((void**)&wql, g_WqL);
    cudaGetSymbolAddress((void**)&wmh, g_WmH); cudaGetSymbolAddress((void**)&wml, g_WmL);
    cudaGetSymbolAddress((void**)&wgh, g_WgH); cudaGetSymbolAddress((void**)&wgl, g_WgL);
    cudaGetSymbolAddress((void**)&wkh, g_WkH); cudaGetSymbolAddress((void**)&wkl, g_WkL);
    cudaGetSymbolAddress((void**)&wvh, g_WvH); cudaGetSymbolAddress((void**)&wvl, g_WvL);
    cudaGetSymbolAddress((void**)&mkh, g_MKH); cudaGetSymbolAddress((void**)&mkl, g_MKL);
    cudaGetSymbolAddress((void**)&mqh, g_MQH); cudaGetSymbolAddress((void**)&mql, g_MQL);
    cudaGetSymbolAddress((void**)&memh, g_MemH); cudaGetSymbolAddress((void**)&meml, g_MemL);
    cudaGetSymbolAddress((void**)&nmh, g_NMemH); cudaGetSymbolAddress((void**)&nml, g_NMemL);

    cudaFuncSetAttribute(gemm_mma<0,256>, cudaFuncAttributeMaxDynamicSharedMemorySize, PJ_SMEM_256);
    cudaFuncSetAttribute(gemm_mma<1,256>, cudaFuncAttributeMaxDynamicSharedMemorySize, PJ_SMEM_256);
    cudaFuncSetAttribute(gemm_mma<0,128>, cudaFuncAttributeMaxDynamicSharedMemorySize, PJ_SMEM_128);
    cudaFuncSetAttribute(gemm_skinny_mma<0>, cudaFuncAttributeMaxDynamicSharedMemorySize, SK_SMEM);
    cudaFuncSetAttribute(gemm_skinny_mma<1>, cudaFuncAttributeMaxDynamicSharedMemorySize, SK_SMEM);
    cudaFuncSetAttribute(gemm_delta_mma, cudaFuncAttributeMaxDynamicSharedMemorySize, DL_SMEM);

    dim3 blk(256);

    // 0) fp32 -> bf16 hi/lo splits
    cvt_split<<<(S * HID / 4 + 255) / 256, blk>>>(X,   xh,  xl,  S * HID / 4);
    cvt_split<<<(HID * HID / 4 + 255) / 256, blk>>>(Wq,  wqh, wql, HID * HID / 4);
    cvt_split<<<(HID * HID / 4 + 255) / 256, blk>>>(Wmb, wmh, wml, HID * HID / 4);
    cvt_split<<<(HID * HID / 4 + 255) / 256, blk>>>(Wg,  wgh, wgl, HID * HID / 4);
    cvt_split<<<(512 * HID / 4 + 255) / 256, blk>>>(Wk,  wkh, wkl, 512 * HID / 4);
    cvt_split<<<(512 * HID / 4 + 255) / 256, blk>>>(Wv,  wvh, wvl, 512 * HID / 4);
    cvt_split<<<(MEM_ELEMS / 4 + 255) / 256, blk>>>(memv, memh, meml, MEM_ELEMS / 4);

    // 1) Projections on tensor cores (big: 128x256 tiles; K/V: 128x128)
    gemm_mma<0,256><<<dim3(HID / 256, S / 128), blk, PJ_SMEM_256>>>(xh, xl, wqh, wql, bq,  pQ,  HID, HID);
    gemm_mma<0,128><<<dim3(512 / 128, S / 128), blk, PJ_SMEM_128>>>(xh, xl, wkh, wkl, bk,  pK,  512, HID);
    gemm_mma<0,128><<<dim3(512 / 128, S / 128), blk, PJ_SMEM_128>>>(xh, xl, wvh, wvl, bv,  pV,  512, HID);
    gemm_mma<1,256><<<dim3(HID / 256, S / 128), blk, PJ_SMEM_256>>>(xh, xl, wmh, wml, bmb, pMB, HID, HID);
    gemm_mma<1,256><<<dim3(HID / 256, S / 128), blk, PJ_SMEM_256>>>(xh, xl, wgh, wgl, bg,  pG,  HID, HID);

    // 2) dpfp + normalize (bf16 hi/lo outputs)
    dpfp_kernel<true ><<<dim3(S, NKV), blk>>>(pK, mkh, mkl, normv);
    dpfp_kernel<false><<<dim3(S, NH ), blk>>>(pQ, mqh, mql, nullptr);

    // 3) num = ext_mk @ memory (tensor cores)
    gemm_skinny_mma<0><<<dim3(S / 128, NH), blk, SK_SMEM>>>(mkh, mkl, 4, memh, meml, pNUM, nullptr);

    // 4) weighted_mv (bf16 hi/lo out)
    wmv_kernel<<<(NH * S * DD) / 256, blk>>>();

    // 5) delta_memory (tensor cores, split-K=4), delta_norm, add
    gemm_delta_mma<<<dim3(FF / 128, 4, NH), blk, DL_SMEM>>>();
    delta_norm_kernel<<<dim3(FF / 64, NKV), blk>>>(normv, out_norm);
    add_delta_kernel<<<MEM_ELEMS / 256, blk>>>(memv, out_mem);

    // 6) associate: num_a GEMM with fused den_a, then output
    gemm_skinny_mma<1><<<dim3(S / 128, NH), blk, SK_SMEM>>>(mqh, mql, 1, nmh, nml, pNUM, out_norm);
    final_kernel<<<OUT_ELEMS / 256, blk>>>(X, out);
}

// round 14
// speedup vs baseline: 1.0108x; 1.0060x over previous
#include <cuda_runtime.h>
#include <cuda_bf16.h>
#include <math.h>
#include <stdint.h>

// ---------------- Problem constants ----------------
#define S      4096
#define HID    2048
#define NH     16
#define NKV    4
#define DD     128
#define FF     768
#define EPSV   1e-8f

#define OUT_ELEMS    (S * HID)
#define MEM_ELEMS    (NH * FF * DD)

// ---------------- Scratch (device globals; no allocation allowed) ----------------
__device__ __align__(16) float g_K  [S * 512];
__device__ __align__(16) float g_V  [S * 512];
__device__ __align__(16) float g_Q  [S * HID];
__device__ __align__(16) float g_MB [S * HID];
__device__ __align__(16) float g_G  [S * HID];
__device__ __align__(16) float g_NUM[(size_t)NH * S * DD];
__device__ __align__(16) float g_DELTA[4][(size_t)NH * FF * DD];
__device__ float g_DEN [NH * S];
__device__ float g_COEF[NH * S];
__device__ float g_DENA[NH * S];

// bf16 split operands
__device__ __align__(16) __nv_bfloat16 g_XH [S * HID];
__device__ __align__(16) __nv_bfloat16 g_XL [S * HID];
__device__ __align__(16) __nv_bfloat16 g_WqH[HID * HID], g_WqL[HID * HID];
__device__ __align__(16) __nv_bfloat16 g_WmH[HID * HID], g_WmL[HID * HID];
__device__ __align__(16) __nv_bfloat16 g_WgH[HID * HID], g_WgL[HID * HID];
__device__ __align__(16) __nv_bfloat16 g_WkH[512 * HID], g_WkL[512 * HID];
__device__ __align__(16) __nv_bfloat16 g_WvH[512 * HID], g_WvL[512 * HID];
__device__ __align__(16) __nv_bfloat16 g_MKH[(size_t)NKV * S * FF], g_MKL[(size_t)NKV * S * FF];
__device__ __align__(16) __nv_bfloat16 g_MQH[(size_t)NH * S * FF], g_MQL[(size_t)NH * S * FF];
__device__ __align__(16) __nv_bfloat16 g_MemH[MEM_ELEMS],  g_MemL[MEM_ELEMS];
__device__ __align__(16) __nv_bfloat16 g_NMemH[MEM_ELEMS], g_NMemL[MEM_ELEMS];
__device__ __align__(16) __nv_bfloat16 g_WMVH[(size_t)NH * S * DD], g_WMVL[(size_t)NH * S * DD];

// ---------------- helpers ----------------
__device__ __forceinline__ float warp_sum(float v) {
#pragma unroll
    for (int o = 16; o > 0; o >>= 1) v += __shfl_down_sync(0xffffffffu, v, o);
    return v;
}
__device__ __forceinline__ uint32_t smem_u32(const void* p) {
    uint32_t a;
    asm("{ .reg .u64 t; cvta.to.shared.u64 t, %1; cvt.u32.u64 %0, t; }"
        : "=r"(a) : "l"(p));
    return a;
}
__device__ __forceinline__ void cp_async16(uint32_t sa, const void* g) {
    asm volatile("cp.async.cg.shared.global [%0], [%1], 16;" :: "r"(sa), "l"(g) : "memory");
}
__device__ __forceinline__ void cp_commit() {
    asm volatile("cp.async.commit_group;" ::: "memory");
}
template<int N> __device__ __forceinline__ void cp_wait() {
    asm volatile("cp.async.wait_group %0;" :: "n"(N) : "memory");
}
__device__ __forceinline__ void ldm_x4(uint32_t* r, uint32_t addr) {
    asm volatile("ldmatrix.sync.aligned.m8n8.x4.shared.b16 {%0,%1,%2,%3}, [%4];"
                 : "=r"(r[0]), "=r"(r[1]), "=r"(r[2]), "=r"(r[3]) : "r"(addr));
}
__device__ __forceinline__ void ldm_x2(uint32_t* r, uint32_t addr) {
    asm volatile("ldmatrix.sync.aligned.m8n8.x2.shared.b16 {%0,%1}, [%2];"
                 : "=r"(r[0]), "=r"(r[1]) : "r"(addr));
}
__device__ __forceinline__ void ldm_x4_t(uint32_t* r, uint32_t addr) {
    asm volatile("ldmatrix.sync.aligned.m8n8.x4.trans.shared.b16 {%0,%1,%2,%3}, [%4];"
                 : "=r"(r[0]), "=r"(r[1]), "=r"(r[2]), "=r"(r[3]) : "r"(addr));
}
__device__ __forceinline__ void ldm_x2_t(uint32_t* r, uint32_t addr) {
    asm volatile("ldmatrix.sync.aligned.m8n8.x2.trans.shared.b16 {%0,%1}, [%2];"
                 : "=r"(r[0]), "=r"(r[1]) : "r"(addr));
}
__device__ __forceinline__ void mma_bf16(float* c, const uint32_t* a, const uint32_t* b) {
    asm volatile(
        "mma.sync.aligned.m16n8k16.row.col.f32.bf16.bf16.f32 "
        "{%0,%1,%2,%3}, {%4,%5,%6,%7}, {%8,%9}, {%0,%1,%2,%3};"
        : "+f"(c[0]), "+f"(c[1]), "+f"(c[2]), "+f"(c[3])
        : "r"(a[0]), "r"(a[1]), "r"(a[2]), "r"(a[3]), "r"(b[0]), "r"(b[1]));
}
__device__ __forceinline__ void split_write(float v, __nv_bfloat16* hp, __nv_bfloat16* lp,
                                            size_t idx) {
    __nv_bfloat16 h = __float2bfloat16(v);
    hp[idx] = h;
    lp[idx] = __float2bfloat16(v - __bfloat162float(h));
}

// ======================================================================
// fp32 -> bf16 hi/lo split conversion (vectorized x4)
// ======================================================================
__global__ void cvt_split(const float* __restrict__ x,
                          __nv_bfloat16* __restrict__ hi,
                          __nv_bfloat16* __restrict__ lo, int n4)
{
    int i = blockIdx.x * 256 + threadIdx.x;
    if (i >= n4) return;
    float4 v = ((const float4*)x)[i];
    __nv_bfloat16 h0 = __float2bfloat16(v.x), h1 = __float2bfloat16(v.y);
    __nv_bfloat16 h2 = __float2bfloat16(v.z), h3 = __float2bfloat16(v.w);
    __nv_bfloat16 l0 = __float2bfloat16(v.x - __bfloat162float(h0));
    __nv_bfloat16 l1 = __float2bfloat16(v.y - __bfloat162float(h1));
    __nv_bfloat16 l2 = __float2bfloat16(v.z - __bfloat162float(h2));
    __nv_bfloat16 l3 = __float2bfloat16(v.w - __bfloat162float(h3));
    __nv_bfloat162* hp = (__nv_bfloat162*)hi;
    __nv_bfloat162* lp = (__nv_bfloat162*)lo;
    hp[2 * i]     = __nv_bfloat162(h0, h1);
    hp[2 * i + 1] = __nv_bfloat162(h2, h3);
    lp[2 * i]     = __nv_bfloat162(l0, l1);
    lp[2 * i + 1] = __nv_bfloat162(l2, l3);
}

// ======================================================================
// Projection GEMM (bf16-split mma.sync): C = A @ W^T + bias (opt sigmoid)
// BM=128, BN template (128 or 256), BK=32, 256 threads, 8 warps (2 x 4),
// warp tile 64 x (BN/4). 3-stage cp.async pipeline, one barrier/chunk.
// ======================================================================
#define PJ_A_T 10240                        // 128 rows * 80B

template <int ACT, int BN>
__global__ __launch_bounds__(256, 1) void gemm_mma(
    const __nv_bfloat16* __restrict__ Ahi, const __nv_bfloat16* __restrict__ Alo,
    const __nv_bfloat16* __restrict__ Bhi, const __nv_bfloat16* __restrict__ Blo,
    const float* __restrict__ bias, float* __restrict__ C, int N, int K)
{
    extern __shared__ char sm[];
    constexpr int NT   = BN / 32;           // nt iterations per warp
    constexpr int B_T  = BN * 80;           // B tile bytes per half
    constexpr int STG  = 2 * PJ_A_T + 2 * B_T;
    const int tid  = threadIdx.x;
    const int lane = tid & 31;
    const int warp = tid >> 5;
    const int wm = warp >> 2;
    const int wn = warp & 3;
    const int bm = blockIdx.y * 128;
    const int bn = blockIdx.x * BN;
    const uint32_t sbase = smem_u32(sm);

    auto load_chunk = [&](int c, int st) {
        const int k0 = c << 5;
        const uint32_t stb = sbase + (uint32_t)st * STG;
#pragma unroll
        for (int half = 0; half < 2; ++half) {
            const __nv_bfloat16* src = (half ? Alo : Ahi) + (size_t)bm * K + k0;
#pragma unroll
            for (int rep = 0; rep < 2; ++rep) {
                int i = tid + rep * 256;
                int r = i >> 2, cc = i & 3;
                cp_async16(stb + (uint32_t)half * PJ_A_T + r * 80 + cc * 16,
                           src + (size_t)r * K + cc * 8);
            }
        }
#pragma unroll
        for (int half = 0; half < 2; ++half) {
            const __nv_bfloat16* src = (half ? Blo : Bhi) + (size_t)bn * K + k0;
#pragma unroll
            for (int rep = 0; rep < BN / 64; ++rep) {
                int i = tid + rep * 256;
                int r = i >> 2, cc = i & 3;
                cp_async16(stb + 2 * PJ_A_T + (uint32_t)half * B_T + r * 80 + cc * 16,
                           src + (size_t)r * K + cc * 8);
            }
        }
        cp_commit();
    };

    float acc[4][NT][4];
#pragma unroll
    for (int mt = 0; mt < 4; ++mt)
#pragma unroll
        for (int nt = 0; nt < NT; ++nt)
#pragma unroll
            for (int r = 0; r < 4; ++r) acc[mt][nt][r] = 0.f;

    const int NC = K >> 5;
    load_chunk(0, 0);
    load_chunk(1, 1);

    for (int c = 0; c < NC; ++c) {
        if (c + 1 < NC) cp_wait<1>(); else cp_wait<0>();
        __syncthreads();
        if (c + 2 < NC) load_chunk(c + 2, (c + 2) % 3);

        const uint32_t stb = sbase + (uint32_t)(c % 3) * STG;
#pragma unroll
        for (int k16 = 0; k16 < 2; ++k16) {
            uint32_t ah[4][4], al[4][4];
#pragma unroll
            for (int mt = 0; mt < 4; ++mt) {
                uint32_t rowa = (uint32_t)(wm * 64 + mt * 16 + (lane & 15));
                uint32_t coff = (uint32_t)((k16 * 16 + ((lane >> 4) << 3)) * 2);
                ldm_x4(ah[mt], stb + 0 * PJ_A_T + rowa * 80 + coff);
                ldm_x4(al[mt], stb + 1 * PJ_A_T + rowa * 80 + coff);
            }
#pragma unroll
            for (int nt = 0; nt < NT; ++nt) {
                uint32_t rowb = (uint32_t)(wn * (BN / 4) + nt * 8 + (lane & 7));
                uint32_t coff = (uint32_t)((k16 * 16 + (((lane >> 3) & 1) << 3)) * 2);
                uint32_t bh[2], bl[2];
                ldm_x2(bh, stb + 2 * PJ_A_T + 0 * B_T + rowb * 80 + coff);
                ldm_x2(bl, stb + 2 * PJ_A_T + 1 * B_T + rowb * 80 + coff);
#pragma unroll
                for (int mt = 0; mt < 4; ++mt) {
                    mma_bf16(acc[mt][nt], ah[mt], bh);
                    mma_bf16(acc[mt][nt], ah[mt], bl);
                    mma_bf16(acc[mt][nt], al[mt], bh);
                }
            }
        }
    }

    const int r0 = bm + wm * 64;
    const int c0 = bn + wn * (BN / 4);
    const int rl = lane >> 2;
    const int cl = (lane & 3) * 2;
#pragma unroll
    for (int mt = 0; mt < 4; ++mt) {
#pragma unroll
        for (int nt = 0; nt < NT; ++nt) {
            int col = c0 + nt * 8 + cl;
            float b0 = bias[col], b1 = bias[col + 1];
#pragma unroll
            for (int half = 0; half < 2; ++half) {
                int row = r0 + mt * 16 + rl + half * 8;
                float v0 = acc[mt][nt][2 * half + 0] + b0;
                float v1 = acc[mt][nt][2 * half + 1] + b1;
                if (ACT) {
                    v0 = 1.f / (1.f + expf(-v0));
                    v1 = 1.f / (1.f + expf(-v1));
                }
                *(float2*)(C + (size_t)row * N + col) = make_float2(v0, v1);
            }
        }
    }
}

#define PJ_SMEM_128 (3 * (2 * PJ_A_T + 2 * 128 * 80))   // 122880
#define PJ_SMEM_256 (3 * (2 * PJ_A_T + 2 * 256 * 80))   // 184320

// ======================================================================
// Skinny einsum GEMM (bf16-split): per head h,
// C[h][tile,128] = A[h/adiv][M,768] @ B[h][768,128].
// 3-stage pipeline. WITHDEN: fuse den_a[s] = dot(mq[s,:], nrm[h,:]) + EPS.
// ======================================================================
#define SK_AT_B 10240                 // A tile: 128 x 80B
#define SK_BT_B 8704                  // B tile: 32 x 272B
#define SK_STAGE (2*SK_AT_B + 2*SK_BT_B)   // 37888
#define SK_SMEM  (3 * SK_STAGE)            // 113664

template <int WITHDEN>
__global__ __launch_bounds__(256, 1) void gemm_skinny_mma(
    const __nv_bfloat16* __restrict__ AH, const __nv_bfloat16* __restrict__ AL,
    int adiv,
    const __nv_bfloat16* __restrict__ BH, const __nv_bfloat16* __restrict__ BL,
    float* __restrict__ Cbase, const float* __restrict__ nrm)
{
    extern __shared__ char sm[];
    const int tid  = threadIdx.x;
    const int lane = tid & 31;
    const int warp = tid >> 5;
    const int wm = warp >> 2;
    const int wn = warp & 3;
    const int h  = blockIdx.y;
    const int bm = blockIdx.x * 128;
    const uint32_t sbase = smem_u32(sm);

    const __nv_bfloat16* Ah = AH + (size_t)(h / adiv) * S * FF;
    const __nv_bfloat16* Al = AL + (size_t)(h / adiv) * S * FF;
    const __nv_bfloat16* Bh = BH + (size_t)h * FF * DD;
    const __nv_bfloat16* Bl = BL + (size_t)h * FF * DD;
    float* C = Cbase + (size_t)h * S * DD;

    auto load_chunk = [&](int c, int st) {
        const int k0 = c << 5;
        const uint32_t stb = sbase + (uint32_t)st * SK_STAGE;
        const __nv_bfloat16* asrc[2] = {Ah, Al};
        const __nv_bfloat16* bsrc[2] = {Bh, Bl};
#pragma unroll
        for (int half = 0; half < 2; ++half) {
#pragma unroll
            for (int rep = 0; rep < 2; ++rep) {
                int i = tid + rep * 256;
                int r = i >> 2, cc = i & 3;
                cp_async16(stb + (uint32_t)half * SK_AT_B + r * 80 + cc * 16,
                           asrc[half] + (size_t)(bm + r) * FF + k0 + cc * 8);
            }
#pragma unroll
            for (int rep = 0; rep < 2; ++rep) {
                int i = tid + rep * 256;
                int r = i >> 4, cc = i & 15;
                cp_async16(stb + 2 * SK_AT_B + (uint32_t)half * SK_BT_B + r * 272 + cc * 16,
                           bsrc[half] + (size_t)(k0 + r) * DD + cc * 8);
            }
        }
        cp_commit();
    };

    float acc[4][4][4];
#pragma unroll
    for (int mt = 0; mt < 4; ++mt)
#pragma unroll
        for (int nt = 0; nt < 4; ++nt)
#pragma unroll
            for (int r = 0; r < 4; ++r) acc[mt][nt][r] = 0.f;

    float den = 0.f;
    const float* nrh = WITHDEN ? (nrm + (size_t)h * FF) : nullptr;

    const int NC = FF >> 5;   // 24
    load_chunk(0, 0);
    load_chunk(1, 1);

    for (int c = 0; c < NC; ++c) {
        if (c + 1 < NC) cp_wait<1>(); else cp_wait<0>();
        __syncthreads();
        if (c + 2 < NC) load_chunk(c + 2, (c + 2) % 3);

        const int st = c % 3;
        const uint32_t stb = sbase + (uint32_t)st * SK_STAGE;

        if (WITHDEN) {
            // den partial: 2 threads per row, 16 cols each, from A smem tiles
            int r = tid >> 1, cs = (tid & 1) * 16;
            const __nv_bfloat16* ph =
                (const __nv_bfloat16*)(sm + (size_t)st * SK_STAGE + (size_t)r * 80);
            const __nv_bfloat16* pl =
                (const __nv_bfloat16*)(sm + (size_t)st * SK_STAGE + SK_AT_B + (size_t)r * 80);
            const float* nr = nrh + (c << 5) + cs;
#pragma unroll
            for (int j = 0; j < 16; ++j) {
                float v = __bfloat162float(ph[cs + j]) + __bfloat162float(pl[cs + j]);
                den = fmaf(v, nr[j], den);
            }
        }

#pragma unroll
        for (int k16 = 0; k16 < 2; ++k16) {
            uint32_t ah[4][4], al[4][4];
#pragma unroll
            for (int mt = 0; mt < 4; ++mt) {
                uint32_t rowa = (uint32_t)(wm * 64 + mt * 16 + (lane & 15));
                uint32_t coff = (uint32_t)((k16 * 16 + ((lane >> 4) << 3)) * 2);
                ldm_x4(ah[mt], stb + 0 * SK_AT_B + rowa * 80 + coff);
                ldm_x4(al[mt], stb + 1 * SK_AT_B + rowa * 80 + coff);
            }
#pragma unroll
            for (int nt = 0; nt < 4; ++nt) {
                uint32_t rowb = (uint32_t)(k16 * 16 + (lane & 15));
                uint32_t noff = (uint32_t)((wn * 32 + nt * 8) * 2);
                uint32_t bh[2], bl[2];
                ldm_x2_t(bh, stb + 2 * SK_AT_B + 0 * SK_BT_B + rowb * 272 + noff);
                ldm_x2_t(bl, stb + 2 * SK_AT_B + 1 * SK_BT_B + rowb * 272 + noff);
#pragma unroll
                for (int mt = 0; mt < 4; ++mt) {
                    mma_bf16(acc[mt][nt], ah[mt], bh);
                    mma_bf16(acc[mt][nt], ah[mt], bl);
                    mma_bf16(acc[mt][nt], al[mt], bh);
                }
            }
        }
    }

    if (WITHDEN) {
        den += __shfl_xor_sync(0xffffffffu, den, 1);
        if (!(tid & 1))
            g_DENA[(size_t)h * S + bm + (tid >> 1)] = den + EPSV;
    }

    const int r0 = bm + wm * 64;
    const int c0 = wn * 32;
    const int rl = lane >> 2;
    const int cl = (lane & 3) * 2;
#pragma unroll
    for (int mt = 0; mt < 4; ++mt)
#pragma unroll
        for (int nt = 0; nt < 4; ++nt) {
            int col = c0 + nt * 8 + cl;
#pragma unroll
            for (int half = 0; half < 2; ++half) {
                int row = r0 + mt * 16 + rl + half * 8;
                *(float2*)(C + (size_t)row * DD + col) =
                    make_float2(acc[mt][nt][2 * half], acc[mt][nt][2 * half + 1]);
            }
        }
}

// ======================================================================
// Delta GEMM (bf16-split, split-K=4), 3-stage pipeline:
// DELTA[part][h][f,d] = sum_{s in part} MK[h/4][s,f] * WMV[h][s,d]
// ======================================================================
#define DL_T_B 8704                   // 32 x 272B
#define DL_STAGE (4 * DL_T_B)         // 34816
#define DL_SMEM  (3 * DL_STAGE)       // 104448

__global__ __launch_bounds__(256, 1) void gemm_delta_mma()
{
    extern __shared__ char sm[];
    const int tid  = threadIdx.x;
    const int lane = tid & 31;
    const int warp = tid >> 5;
    const int wm = warp >> 2;
    const int wn = warp & 3;
    const int h    = blockIdx.z;
    const int part = blockIdx.y;
    const int f0   = blockIdx.x * 128;
    const uint32_t sbase = smem_u32(sm);

    const __nv_bfloat16* Ah = g_MKH + (size_t)(h >> 2) * S * FF;
    const __nv_bfloat16* Al = g_MKL + (size_t)(h >> 2) * S * FF;
    const __nv_bfloat16* Bh = g_WMVH + (size_t)h * S * DD;
    const __nv_bfloat16* Bl = g_WMVL + (size_t)h * S * DD;

    const int kbase = part * (S / 4);

    auto load_chunk = [&](int c, int st) {
        const int k0 = kbase + (c << 5);
        const uint32_t stb = sbase + (uint32_t)st * DL_STAGE;
        const __nv_bfloat16* srcs[4] = {Ah, Al, Bh, Bl};
#pragma unroll
        for (int tile = 0; tile < 4; ++tile) {
            const bool isA = tile < 2;
#pragma unroll
            for (int rep = 0; rep < 2; ++rep) {
                int i = tid + rep * 256;
                int r = i >> 4, cc = i & 15;
                const __nv_bfloat16* src = isA
                    ? srcs[tile] + (size_t)(k0 + r) * FF + f0 + cc * 8
                    : srcs[tile] + (size_t)(k0 + r) * DD + cc * 8;
                cp_async16(stb + (uint32_t)tile * DL_T_B + r * 272 + cc * 16, src);
            }
        }
        cp_commit();
    };

    float acc[4][4][4];
#pragma unroll
    for (int mt = 0; mt < 4; ++mt)
#pragma unroll
        for (int nt = 0; nt < 4; ++nt)
#pragma unroll
            for (int r = 0; r < 4; ++r) acc[mt][nt][r] = 0.f;

    const int NC = (S / 4) >> 5;   // 32
    load_chunk(0, 0);
    load_chunk(1, 1);

    for (int c = 0; c < NC; ++c) {
        if (c + 1 < NC) cp_wait<1>(); else cp_wait<0>();
        __syncthreads();
        if (c + 2 < NC) load_chunk(c + 2, (c + 2) % 3);

        const uint32_t stb = sbase + (uint32_t)(c % 3) * DL_STAGE;
#pragma unroll
        for (int k16 = 0; k16 < 2; ++k16) {
            uint32_t ah[4][4], al[4][4];
            uint32_t rowa = (uint32_t)(k16 * 16 + (lane & 7) + ((lane >> 4) << 3));
#pragma unroll
            for (int mt = 0; mt < 4; ++mt) {
                uint32_t cola = (uint32_t)((wm * 64 + mt * 16 + (((lane >> 3) & 1) << 3)) * 2);
                ldm_x4_t(ah[mt], stb + 0 * DL_T_B + rowa * 272 + cola);
                ldm_x4_t(al[mt], stb + 1 * DL_T_B + rowa * 272 + cola);
            }
#pragma unroll
            for (int nt = 0; nt < 4; ++nt) {
                uint32_t rowb = (uint32_t)(k16 * 16 + (lane & 15));
                uint32_t noff = (uint32_t)((wn * 32 + nt * 8) * 2);
                uint32_t bh[2], bl[2];
                ldm_x2_t(bh, stb + 2 * DL_T_B + rowb * 272 + noff);
                ldm_x2_t(bl, stb + 3 * DL_T_B + rowb * 272 + noff);
#pragma unroll
                for (int mt = 0; mt < 4; ++mt) {
                    mma_bf16(acc[mt][nt], ah[mt], bh);
                    mma_bf16(acc[mt][nt], ah[mt], bl);
                    mma_bf16(acc[mt][nt], al[mt], bh);
                }
            }
        }
    }

    float* Cp = g_DELTA[part] + (size_t)h * FF * DD;
    const int r0 = f0 + wm * 64;
    const int c0 = wn * 32;
    const int rl = lane >> 2;
    const int cl = (lane & 3) * 2;
#pragma unroll
    for (int mt = 0; mt < 4; ++mt)
#pragma unroll
        for (int nt = 0; nt < 4; ++nt) {
            int col = c0 + nt * 8 + cl;
#pragma unroll
            for (int half = 0; half < 2; ++half) {
                int row = r0 + mt * 16 + rl + half * 8;
                *(float2*)(Cp + (size_t)row * DD + col) =
                    make_float2(acc[mt][nt][2 * half], acc[mt][nt][2 * half + 1]);
            }
        }
}

// ======================================================================
// dpfp + L2-normalize, emits bf16 hi/lo. K variant fuses denom/coef.
// ======================================================================
template <bool WITHDEN>
__global__ __launch_bounds__(256) void dpfp_kernel(
    const float* __restrict__ X,
    __nv_bfloat16* __restrict__ outh, __nv_bfloat16* __restrict__ outl,
    const float* __restrict__ normv)
{
    const int s  = blockIdx.x;
    const int hh = blockIdx.y;
    const int nh = gridDim.y;
    const int t  = threadIdx.x;
    __shared__ float y[256];
    __shared__ float red[5][8];

    const float* x = X + ((size_t)s * nh + hh) * 128;
    float xv = (t < 128) ? x[t] : -x[t - 128];
    y[t] = fmaxf(xv, 0.f);
    __syncthreads();

    float yi = y[t];
    float m0 = yi * y[(t - 1) & 255];
    float m1 = yi * y[(t - 2) & 255];
    float m2 = yi * y[(t - 3) & 255];
    float ss = m0 * m0 + m1 * m1 + m2 * m2;

    float dd[4];
    if (WITHDEN) {
#pragma unroll
        for (int g = 0; g < 4; g++) {
            const float* nr = normv + (size_t)(4 * hh + g) * FF;
            dd[g] = m0 * nr[t] + m1 * nr[256 + t] + m2 * nr[512 + t];
        }
    }

    const int lane = t & 31, w = t >> 5;
    float r0 = warp_sum(ss);
    if (lane == 0) red[0][w] = r0;
    if (WITHDEN) {
#pragma unroll
        for (int g = 0; g < 4; g++) {
            float rg = warp_sum(dd[g]);
            if (lane == 0) red[1 + g][w] = rg;
        }
    }
    __syncthreads();

    float ssT = 0.f;
#pragma unroll
    for (int w2 = 0; w2 < 8; w2++) ssT += red[0][w2];
    float nrm = sqrtf(ssT);
    float inv = 1.f / fmaxf(nrm, 1e-12f);

    size_t base = ((size_t)hh * S + s) * FF;
    split_write(m0 * inv, outh, outl, base + t);
    split_write(m1 * inv, outh, outl, base + 256 + t);
    split_write(m2 * inv, outh, outl, base + 512 + t);

    if (WITHDEN && t < 4) {
        float dT = 0.f;
#pragma unroll
        for (int w2 = 0; w2 < 8; w2++) dT += red[1 + t][w2];
        float den  = dT * inv + EPSV;
        float mksq = ssT * inv * inv;
        float coef = 1.f - den / mksq;
        coef = fminf(fmaxf(coef, 0.f), 1.f);
        int h = 4 * hh + t;
        g_DEN[h * S + s]  = den;
        g_COEF[h * S + s] = coef;
    }
}

// weighted_mv = (v - num/denom) * mb -> bf16 hi/lo
__global__ void wmv_kernel()
{
    size_t idx = (size_t)blockIdx.x * 256 + threadIdx.x;
    int h = (int)(idx >> 19);
    size_t r = idx & ((1u << 19) - 1);
    int s  = (int)(r >> 7);
    int d0 = (int)(r & 127);
    float den  = g_DEN[h * S + s];
    float prev = g_NUM[idx] / den;
    float v  = g_V[(size_t)s * 512 + (size_t)(h >> 2) * 128 + d0];
    float mb = g_MB[(size_t)s * HID + (size_t)h * 128 + d0];
    split_write((v - prev) * mb, g_WMVH, g_WMVL, idx);
}

// new_norm[h][f] = norm[h][f] + sum_s coef[h][s]*MK[h/4][s][f]   (MK = hi+lo)
__global__ __launch_bounds__(256) void delta_norm_kernel(
    const float* __restrict__ normv, float* __restrict__ out_norm)
{
    const int kv = blockIdx.y;
    const int f0 = blockIdx.x * 64;
    const int t  = threadIdx.x;
    const int fl = t & 63, sl = t >> 6;

    float acc[4] = {0.f, 0.f, 0.f, 0.f};
    const __nv_bfloat16* mh = g_MKH + (size_t)kv * S * FF + f0 + fl;
    const __nv_bfloat16* ml = g_MKL + (size_t)kv * S * FF + f0 + fl;
    for (int s = sl; s < S; s += 4) {
        float v = __bfloat162float(mh[(size_t)s * FF]) + __bfloat162float(ml[(size_t)s * FF]);
#pragma unroll
        for (int g = 0; g < 4; g++)
            acc[g] = fmaf(g_COEF[(4 * kv + g) * S + s], v, acc[g]);
    }
    __shared__ float smr[4][4][64];
#pragma unroll
    for (int g = 0; g < 4; g++) smr[sl][g][fl] = acc[g];
    __syncthreads();
    if (t < 64) {
#pragma unroll
        for (int g = 0; g < 4; g++) {
            float sum = smr[0][g][t] + smr[1][g][t] + smr[2][g][t] + smr[3][g][t];
            int h = 4 * kv + g;
            out_norm[(size_t)h * FF + f0 + t] = normv[(size_t)h * FF + f0 + t] + sum;
        }
    }
}

// new_memory = memory + sum partials; also emit hi/lo bf16
__global__ void add_delta_kernel(const float* __restrict__ memory,
                                 float* __restrict__ out_mem)
{
    size_t idx = (size_t)blockIdx.x * 256 + threadIdx.x;
    float v = memory[idx] + g_DELTA[0][idx] + g_DELTA[1][idx]
            + g_DELTA[2][idx] + g_DELTA[3][idx];
    out_mem[idx] = v;
    split_write(v, g_NMemH, g_NMemL, idx);
}

__global__ void final_kernel(const float* __restrict__ X, float* __restrict__ out)
{
    size_t idx = (size_t)blockIdx.x * 256 + threadIdx.x;
    int s  = (int)(idx >> 11);
    int c  = (int)(idx & 2047);
    int h  = c >> 7;
    int d0 = c & 127;
    float numa = g_NUM[((size_t)h * S + s) * DD + d0];
    float mh = numa / g_DENA[h * S + s];
    out[idx] = X[idx] + g_G[idx] * mh;
}

// ======================================================================
// Launch
// ======================================================================
extern "C" void kernel_launch(void* const* d_in, const int* in_sizes, int n_in,
                              void* d_out, int out_size)
{
    const float* X    = (const float*)d_in[0];
    const float* Wq   = (const float*)d_in[1];
    const float* bq   = (const float*)d_in[2];
    const float* Wk   = (const float*)d_in[3];
    const float* bk   = (const float*)d_in[4];
    const float* Wv   = (const float*)d_in[5];
    const float* bv   = (const float*)d_in[6];
    const float* Wg   = (const float*)d_in[7];
    const float* bg   = (const float*)d_in[8];
    const float* Wmb  = (const float*)d_in[9];
    const float* bmb  = (const float*)d_in[10];
    const float* memv = (const float*)d_in[11];
    const float* normv= (const float*)d_in[12];

    float* out      = (float*)d_out;
    float* out_mem  = out + OUT_ELEMS;
    float* out_norm = out_mem + MEM_ELEMS;

    float *pK, *pV, *pQ, *pMB, *pG, *pNUM;
    cudaGetSymbolAddress((void**)&pK,  g_K);
    cudaGetSymbolAddress((void**)&pV,  g_V);
    cudaGetSymbolAddress((void**)&pQ,  g_Q);
    cudaGetSymbolAddress((void**)&pMB, g_MB);
    cudaGetSymbolAddress((void**)&pG,  g_G);
    cudaGetSymbolAddress((void**)&pNUM, g_NUM);

    __nv_bfloat16 *xh, *xl, *wqh, *wql, *wmh, *wml, *wgh, *wgl, *wkh, *wkl, *wvh, *wvl;
    __nv_bfloat16 *mkh, *mkl, *mqh, *mql, *memh, *meml, *nmh, *nml;
    cudaGetSymbolAddress((void**)&xh,  g_XH);  cudaGetSymbolAddress((void**)&xl,  g_XL);
    cudaGetSymbolAddress((void**)&wqh, g_WqH); cudaGetSymbolAddress((void**)&wql, g_WqL);
    cudaGetSymbolAddress((void**)&wmh, g_WmH); cudaGetSymbolAddress((void**)&wml, g_WmL);
    cudaGetSymbolAddress((void**)&wgh, g_WgH); cudaGetSymbolAddress((void**)&wgl, g_WgL);
    cudaGetSymbolAddress((void**)&wkh, g_WkH); cudaGetSymbolAddress((void**)&wkl, g_WkL);
    cudaGetSymbolAddress((void**)&wvh, g_WvH); cudaGetSymbolAddress((void**)&wvl, g_WvL);
    cudaGetSymbolAddress((void**)&mkh, g_MKH); cudaGetSymbolAddress((void**)&mkl, g_MKL);
    cudaGetSymbolAddress((void**)&mqh, g_MQH); cudaGetSymbolAddress((void**)&mql, g_MQL);
    cudaGetSymbolAddress((void**)&memh, g_MemH); cudaGetSymbolAddress((void**)&meml, g_MemL);
    cudaGetSymbolAddress((void**)&nmh, g_NMemH); cudaGetSymbolAddress((void**)&nml, g_NMemL);

    cudaFuncSetAttribute(gemm_mma<0,256>, cudaFuncAttributeMaxDynamicSharedMemorySize, PJ_SMEM_256);
    cudaFuncSetAttribute(gemm_mma<1,256>, cudaFuncAttributeMaxDynamicSharedMemorySize, PJ_SMEM_256);
    cudaFuncSetAttribute(gemm_mma<0,128>, cudaFuncAttributeMaxDynamicSharedMemorySize, PJ_SMEM_128);
    cudaFuncSetAttribute(gemm_skinny_mma<0>, cudaFuncAttributeMaxDynamicSharedMemorySize, SK_SMEM);
    cudaFuncSetAttribute(gemm_skinny_mma<1>, cudaFuncAttributeMaxDynamicSharedMemorySize, SK_SMEM);
    cudaFuncSetAttribute(gemm_delta_mma, cudaFuncAttributeMaxDynamicSharedMemorySize, DL_SMEM);

    dim3 blk(256);

    // 0) fp32 -> bf16 hi/lo splits
    cvt_split<<<(S * HID / 4 + 255) / 256, blk>>>(X,   xh,  xl,  S * HID / 4);
    cvt_split<<<(HID * HID / 4 + 255) / 256, blk>>>(Wq,  wqh, wql, HID * HID / 4);
    cvt_split<<<(HID * HID / 4 + 255) / 256, blk>>>(Wmb, wmh, wml, HID * HID / 4);
    cvt_split<<<(HID * HID / 4 + 255) / 256, blk>>>(Wg,  wgh, wgl, HID * HID / 4);
    cvt_split<<<(512 * HID / 4 + 255) / 256, blk>>>(Wk,  wkh, wkl, 512 * HID / 4);
    cvt_split<<<(512 * HID / 4 + 255) / 256, blk>>>(Wv,  wvh, wvl, 512 * HID / 4);
    cvt_split<<<(MEM_ELEMS / 4 + 255) / 256, blk>>>(memv, memh, meml, MEM_ELEMS / 4);

    // 1) Projections on tensor cores (big: 128x256 tiles; K/V: 128x128)
    gemm_mma<0,256><<<dim3(HID / 256, S / 128), blk, PJ_SMEM_256>>>(xh, xl, wqh, wql, bq,  pQ,  HID, HID);
    gemm_mma<0,128><<<dim3(512 / 128, S / 128), blk, PJ_SMEM_128>>>(xh, xl, wkh, wkl, bk,  pK,  512, HID);
    gemm_mma<0,128><<<dim3(512 / 128, S / 128), blk, PJ_SMEM_128>>>(xh, xl, wvh, wvl, bv,  pV,  512, HID);
    gemm_mma<1,256><<<dim3(HID / 256, S / 128), blk, PJ_SMEM_256>>>(xh, xl, wmh, wml, bmb, pMB, HID, HID);
    gemm_mma<1,256><<<dim3(HID / 256, S / 128), blk, PJ_SMEM_256>>>(xh, xl, wgh, wgl, bg,  pG,  HID, HID);

    // 2) dpfp + normalize (bf16 hi/lo outputs)
    dpfp_kernel<true ><<<dim3(S, NKV), blk>>>(pK, mkh, mkl, normv);
    dpfp_kernel<false><<<dim3(S, NH ), blk>>>(pQ, mqh, mql, nullptr);

    // 3) num = ext_mk @ memory (tensor cores)
    gemm_skinny_mma<0><<<dim3(S / 128, NH), blk, SK_SMEM>>>(mkh, mkl, 4, memh, meml, pNUM, nullptr);

    // 4) weighted_mv (bf16 hi/lo out)
    wmv_kernel<<<(NH * S * DD) / 256, blk>>>();

    // 5) delta_memory (tensor cores, split-K=4), delta_norm, add
    gemm_delta_mma<<<dim3(FF / 128, 4, NH), blk, DL_SMEM>>>();
    delta_norm_kernel<<<dim3(FF / 64, NKV), blk>>>(normv, out_norm);
    add_delta_kernel<<<MEM_ELEMS / 256, blk>>>(memv, out_mem);

    // 6) associate: num_a GEMM with fused den_a, then output
    gemm_skinny_mma<1><<<dim3(S / 128, NH), blk, SK_SMEM>>>(mqh, mql, 1, nmh, nml, pNUM, out_norm);
    final_kernel<<<OUT_ELEMS / 256, blk>>>(X, out);
}

// round 15
// speedup vs baseline: 1.0764x; 1.0649x over previous
#include <cuda_runtime.h>
#include <cuda_bf16.h>
#include <math.h>
#include <stdint.h>

// ---------------- Problem constants ----------------
#define S      4096
#define HID    2048
#define NH     16
#define NKV    4
#define DD     128
#define FF     768
#define EPSV   1e-8f

#define OUT_ELEMS    (S * HID)
#define MEM_ELEMS    (NH * FF * DD)

// ---------------- Scratch (device globals; no allocation allowed) ----------------
__device__ __align__(16) float g_K  [S * 512];
__device__ __align__(16) float g_V  [S * 512];
__device__ __align__(16) float g_Q  [S * HID];
__device__ __align__(16) float g_MB [S * HID];
__device__ __align__(16) float g_G  [S * HID];
__device__ __align__(16) float g_DELTA[4][(size_t)NH * FF * DD];
__device__ float g_DEN [NH * S];
__device__ float g_COEF[NH * S];

// bf16 split operands
__device__ __align__(16) __nv_bfloat16 g_XH [S * HID];
__device__ __align__(16) __nv_bfloat16 g_XL [S * HID];
__device__ __align__(16) __nv_bfloat16 g_WqH[HID * HID], g_WqL[HID * HID];
__device__ __align__(16) __nv_bfloat16 g_WmH[HID * HID], g_WmL[HID * HID];
__device__ __align__(16) __nv_bfloat16 g_WgH[HID * HID], g_WgL[HID * HID];
__device__ __align__(16) __nv_bfloat16 g_WkH[512 * HID], g_WkL[512 * HID];
__device__ __align__(16) __nv_bfloat16 g_WvH[512 * HID], g_WvL[512 * HID];
__device__ __align__(16) __nv_bfloat16 g_MKH[(size_t)NKV * S * FF], g_MKL[(size_t)NKV * S * FF];
__device__ __align__(16) __nv_bfloat16 g_MQH[(size_t)NH * S * FF], g_MQL[(size_t)NH * S * FF];
__device__ __align__(16) __nv_bfloat16 g_MemH[MEM_ELEMS],  g_MemL[MEM_ELEMS];
__device__ __align__(16) __nv_bfloat16 g_NMemH[MEM_ELEMS], g_NMemL[MEM_ELEMS];
__device__ __align__(16) __nv_bfloat16 g_WMVH[(size_t)NH * S * DD], g_WMVL[(size_t)NH * S * DD];

// ---------------- helpers ----------------
__device__ __forceinline__ float warp_sum(float v) {
#pragma unroll
    for (int o = 16; o > 0; o >>= 1) v += __shfl_down_sync(0xffffffffu, v, o);
    return v;
}
__device__ __forceinline__ uint32_t smem_u32(const void* p) {
    uint32_t a;
    asm("{ .reg .u64 t; cvta.to.shared.u64 t, %1; cvt.u32.u64 %0, t; }"
        : "=r"(a) : "l"(p));
    return a;
}
__device__ __forceinline__ void cp_async16(uint32_t sa, const void* g) {
    asm volatile("cp.async.cg.shared.global [%0], [%1], 16;" :: "r"(sa), "l"(g) : "memory");
}
__device__ __forceinline__ void cp_commit() {
    asm volatile("cp.async.commit_group;" ::: "memory");
}
template<int N> __device__ __forceinline__ void cp_wait() {
    asm volatile("cp.async.wait_group %0;" :: "n"(N) : "memory");
}
__device__ __forceinline__ void ldm_x4(uint32_t* r, uint32_t addr) {
    asm volatile("ldmatrix.sync.aligned.m8n8.x4.shared.b16 {%0,%1,%2,%3}, [%4];"
                 : "=r"(r[0]), "=r"(r[1]), "=r"(r[2]), "=r"(r[3]) : "r"(addr));
}
__device__ __forceinline__ void ldm_x2(uint32_t* r, uint32_t addr) {
    asm volatile("ldmatrix.sync.aligned.m8n8.x2.shared.b16 {%0,%1}, [%2];"
                 : "=r"(r[0]), "=r"(r[1]) : "r"(addr));
}
__device__ __forceinline__ void ldm_x4_t(uint32_t* r, uint32_t addr) {
    asm volatile("ldmatrix.sync.aligned.m8n8.x4.trans.shared.b16 {%0,%1,%2,%3}, [%4];"
                 : "=r"(r[0]), "=r"(r[1]), "=r"(r[2]), "=r"(r[3]) : "r"(addr));
}
__device__ __forceinline__ void ldm_x2_t(uint32_t* r, uint32_t addr) {
    asm volatile("ldmatrix.sync.aligned.m8n8.x2.trans.shared.b16 {%0,%1}, [%2];"
                 : "=r"(r[0]), "=r"(r[1]) : "r"(addr));
}
__device__ __forceinline__ void mma_bf16(float* c, const uint32_t* a, const uint32_t* b) {
    asm volatile(
        "mma.sync.aligned.m16n8k16.row.col.f32.bf16.bf16.f32 "
        "{%0,%1,%2,%3}, {%4,%5,%6,%7}, {%8,%9}, {%0,%1,%2,%3};"
        : "+f"(c[0]), "+f"(c[1]), "+f"(c[2]), "+f"(c[3])
        : "r"(a[0]), "r"(a[1]), "r"(a[2]), "r"(a[3]), "r"(b[0]), "r"(b[1]));
}
__device__ __forceinline__ void split_write(float v, __nv_bfloat16* hp, __nv_bfloat16* lp,
                                            size_t idx) {
    __nv_bfloat16 h = __float2bfloat16(v);
    hp[idx] = h;
    lp[idx] = __float2bfloat16(v - __bfloat162float(h));
}

// ======================================================================
// Batched fp32 -> bf16 hi/lo split (one launch for all tensors)
// ======================================================================
struct CvtSeg { const float* x; __nv_bfloat16* h; __nv_bfloat16* l; int n4; };
struct CvtArgs { CvtSeg s[7]; };

__global__ void cvt_split_multi(CvtArgs a, int total4)
{
    int i = blockIdx.x * 256 + threadIdx.x;
    if (i >= total4) return;
    int seg = 0, off = i;
#pragma unroll
    for (int k = 0; k < 6; ++k)
        if (off >= a.s[seg].n4) { off -= a.s[seg].n4; seg++; }

    float4 v = ((const float4*)a.s[seg].x)[off];
    __nv_bfloat16 h0 = __float2bfloat16(v.x), h1 = __float2bfloat16(v.y);
    __nv_bfloat16 h2 = __float2bfloat16(v.z), h3 = __float2bfloat16(v.w);
    __nv_bfloat16 l0 = __float2bfloat16(v.x - __bfloat162float(h0));
    __nv_bfloat16 l1 = __float2bfloat16(v.y - __bfloat162float(h1));
    __nv_bfloat16 l2 = __float2bfloat16(v.z - __bfloat162float(h2));
    __nv_bfloat16 l3 = __float2bfloat16(v.w - __bfloat162float(h3));
    __nv_bfloat162* hp = (__nv_bfloat162*)a.s[seg].h;
    __nv_bfloat162* lp = (__nv_bfloat162*)a.s[seg].l;
    hp[2 * off]     = __nv_bfloat162(h0, h1);
    hp[2 * off + 1] = __nv_bfloat162(h2, h3);
    lp[2 * off]     = __nv_bfloat162(l0, l1);
    lp[2 * off + 1] = __nv_bfloat162(l2, l3);
}

// ======================================================================
// Merged projection GEMM (ALL 5 projections, one launch):
// C = X @ W^T + bias (opt sigmoid). BM=128, BN=256, BK=32, 8 warps,
// 3-stage cp.async pipeline. blockIdx.x in [0,28): Q(8)+MB(8)+G(8)+K(2)+V(2).
// ======================================================================
#define PJ_A_T 10240                        // 128 rows * 80B
#define PJ_B_T (256 * 80)
#define PJ_STG (2 * PJ_A_T + 2 * PJ_B_T)
#define PJ_SMEM (3 * PJ_STG)                // 184320

struct ProjSeg { const __nv_bfloat16* wh; const __nv_bfloat16* wl;
                 const float* bias; float* C; int N; int act; };
struct ProjArgs { ProjSeg s[5]; };

__global__ __launch_bounds__(256, 1) void gemm_proj(
    const __nv_bfloat16* __restrict__ Ahi, const __nv_bfloat16* __restrict__ Alo,
    ProjArgs pa)
{
    extern __shared__ char sm[];
    const int tid  = threadIdx.x;
    const int lane = tid & 31;
    const int warp = tid >> 5;
    const int wm = warp >> 2;
    const int wn = warp & 3;

    int bx = blockIdx.x, seg, nb;
    if (bx < 24)      { seg = bx >> 3; nb = bx & 7; }
    else if (bx < 26) { seg = 3; nb = bx - 24; }
    else              { seg = 4; nb = bx - 26; }
    const ProjSeg ps = pa.s[seg];

    const int bm = blockIdx.y * 128;
    const int bn = nb * 256;
    const int K  = HID;
    const uint32_t sbase = smem_u32(sm);

    auto load_chunk = [&](int c, int st) {
        const int k0 = c << 5;
        const uint32_t stb = sbase + (uint32_t)st * PJ_STG;
#pragma unroll
        for (int half = 0; half < 2; ++half) {
            const __nv_bfloat16* src = (half ? Alo : Ahi) + (size_t)bm * K + k0;
#pragma unroll
            for (int rep = 0; rep < 2; ++rep) {
                int i = tid + rep * 256;
                int r = i >> 2, cc = i & 3;
                cp_async16(stb + (uint32_t)half * PJ_A_T + r * 80 + cc * 16,
                           src + (size_t)r * K + cc * 8);
            }
        }
#pragma unroll
        for (int half = 0; half < 2; ++half) {
            const __nv_bfloat16* src = (half ? ps.wl : ps.wh) + (size_t)bn * K + k0;
#pragma unroll
            for (int rep = 0; rep < 4; ++rep) {
                int i = tid + rep * 256;
                int r = i >> 2, cc = i & 3;
                cp_async16(stb + 2 * PJ_A_T + (uint32_t)half * PJ_B_T + r * 80 + cc * 16,
                           src + (size_t)r * K + cc * 8);
            }
        }
        cp_commit();
    };

    float acc[4][8][4];
#pragma unroll
    for (int mt = 0; mt < 4; ++mt)
#pragma unroll
        for (int nt = 0; nt < 8; ++nt)
#pragma unroll
            for (int r = 0; r < 4; ++r) acc[mt][nt][r] = 0.f;

    const int NC = K >> 5;   // 64
    load_chunk(0, 0);
    load_chunk(1, 1);

    for (int c = 0; c < NC; ++c) {
        if (c + 1 < NC) cp_wait<1>(); else cp_wait<0>();
        __syncthreads();
        if (c + 2 < NC) load_chunk(c + 2, (c + 2) % 3);

        const uint32_t stb = sbase + (uint32_t)(c % 3) * PJ_STG;
#pragma unroll
        for (int k16 = 0; k16 < 2; ++k16) {
            uint32_t ah[4][4], al[4][4];
#pragma unroll
            for (int mt = 0; mt < 4; ++mt) {
                uint32_t rowa = (uint32_t)(wm * 64 + mt * 16 + (lane & 15));
                uint32_t coff = (uint32_t)((k16 * 16 + ((lane >> 4) << 3)) * 2);
                ldm_x4(ah[mt], stb + 0 * PJ_A_T + rowa * 80 + coff);
                ldm_x4(al[mt], stb + 1 * PJ_A_T + rowa * 80 + coff);
            }
#pragma unroll
            for (int nt = 0; nt < 8; ++nt) {
                uint32_t rowb = (uint32_t)(wn * 64 + nt * 8 + (lane & 7));
                uint32_t coff = (uint32_t)((k16 * 16 + (((lane >> 3) & 1) << 3)) * 2);
                uint32_t bh[2], bl[2];
                ldm_x2(bh, stb + 2 * PJ_A_T + 0 * PJ_B_T + rowb * 80 + coff);
                ldm_x2(bl, stb + 2 * PJ_A_T + 1 * PJ_B_T + rowb * 80 + coff);
#pragma unroll
                for (int mt = 0; mt < 4; ++mt) {
                    mma_bf16(acc[mt][nt], ah[mt], bh);
                    mma_bf16(acc[mt][nt], ah[mt], bl);
                    mma_bf16(acc[mt][nt], al[mt], bh);
                }
            }
        }
    }

    const int r0 = bm + wm * 64;
    const int c0 = bn + wn * 64;
    const int rl = lane >> 2;
    const int cl = (lane & 3) * 2;
    const int act = ps.act;
    float* C = ps.C;
    const int N = ps.N;
#pragma unroll
    for (int mt = 0; mt < 4; ++mt) {
#pragma unroll
        for (int nt = 0; nt < 8; ++nt) {
            int col = c0 + nt * 8 + cl;
            float b0 = ps.bias[col], b1 = ps.bias[col + 1];
#pragma unroll
            for (int half = 0; half < 2; ++half) {
                int row = r0 + mt * 16 + rl + half * 8;
                float v0 = acc[mt][nt][2 * half + 0] + b0;
                float v1 = acc[mt][nt][2 * half + 1] + b1;
                if (act) {
                    v0 = 1.f / (1.f + expf(-v0));
                    v1 = 1.f / (1.f + expf(-v1));
                }
                *(float2*)(C + (size_t)row * N + col) = make_float2(v0, v1);
            }
        }
    }
}

// ======================================================================
// Skinny einsum GEMM (bf16-split), 3-stage pipeline.
// MODE 0 (update): C = MK @ memory; epilogue fuses wmv:
//     WMV = (V - num/DEN) * MB  -> bf16 hi/lo   (no fp32 C written)
// MODE 1 (associate): C = MQ @ new_memory; fuses den_a from A smem tiles,
//     epilogue writes out = X + G * (num/den_a) directly.
// ======================================================================
#define SK_AT_B 10240                 // A tile: 128 x 80B
#define SK_BT_B 8704                  // B tile: 32 x 272B
#define SK_STAGE (2*SK_AT_B + 2*SK_BT_B)   // 37888
#define SK_SMEM  (3 * SK_STAGE)            // 113664

template <int MODE>
__global__ __launch_bounds__(256, 1) void gemm_skinny_mma(
    const __nv_bfloat16* __restrict__ AH, const __nv_bfloat16* __restrict__ AL,
    int adiv,
    const __nv_bfloat16* __restrict__ BH, const __nv_bfloat16* __restrict__ BL,
    const float* __restrict__ nrm,
    const float* __restrict__ Xg, const float* __restrict__ Gg,
    float* __restrict__ outg)
{
    extern __shared__ char sm[];
    __shared__ float densm[128];
    const int tid  = threadIdx.x;
    const int lane = tid & 31;
    const int warp = tid >> 5;
    const int wm = warp >> 2;
    const int wn = warp & 3;
    const int h  = blockIdx.y;
    const int bm = blockIdx.x * 128;
    const uint32_t sbase = smem_u32(sm);

    const __nv_bfloat16* Ah = AH + (size_t)(h / adiv) * S * FF;
    const __nv_bfloat16* Al = AL + (size_t)(h / adiv) * S * FF;
    const __nv_bfloat16* Bh = BH + (size_t)h * FF * DD;
    const __nv_bfloat16* Bl = BL + (size_t)h * FF * DD;

    auto load_chunk = [&](int c, int st) {
        const int k0 = c << 5;
        const uint32_t stb = sbase + (uint32_t)st * SK_STAGE;
        const __nv_bfloat16* asrc[2] = {Ah, Al};
        const __nv_bfloat16* bsrc[2] = {Bh, Bl};
#pragma unroll
        for (int half = 0; half < 2; ++half) {
#pragma unroll
            for (int rep = 0; rep < 2; ++rep) {
                int i = tid + rep * 256;
                int r = i >> 2, cc = i & 3;
                cp_async16(stb + (uint32_t)half * SK_AT_B + r * 80 + cc * 16,
                           asrc[half] + (size_t)(bm + r) * FF + k0 + cc * 8);
            }
#pragma unroll
            for (int rep = 0; rep < 2; ++rep) {
                int i = tid + rep * 256;
                int r = i >> 4, cc = i & 15;
                cp_async16(stb + 2 * SK_AT_B + (uint32_t)half * SK_BT_B + r * 272 + cc * 16,
                           bsrc[half] + (size_t)(k0 + r) * DD + cc * 8);
            }
        }
        cp_commit();
    };

    float acc[4][4][4];
#pragma unroll
    for (int mt = 0; mt < 4; ++mt)
#pragma unroll
        for (int nt = 0; nt < 4; ++nt)
#pragma unroll
            for (int r = 0; r < 4; ++r) acc[mt][nt][r] = 0.f;

    float den = 0.f;
    const float* nrh = (MODE == 1) ? (nrm + (size_t)h * FF) : nullptr;

    const int NC = FF >> 5;   // 24
    load_chunk(0, 0);
    load_chunk(1, 1);

    for (int c = 0; c < NC; ++c) {
        if (c + 1 < NC) cp_wait<1>(); else cp_wait<0>();
        __syncthreads();
        if (c + 2 < NC) load_chunk(c + 2, (c + 2) % 3);

        const int st = c % 3;
        const uint32_t stb = sbase + (uint32_t)st * SK_STAGE;

        if (MODE == 1) {
            int r = tid >> 1, cs = (tid & 1) * 16;
            const __nv_bfloat16* ph =
                (const __nv_bfloat16*)(sm + (size_t)st * SK_STAGE + (size_t)r * 80);
            const __nv_bfloat16* pl =
                (const __nv_bfloat16*)(sm + (size_t)st * SK_STAGE + SK_AT_B + (size_t)r * 80);
            const float* nr = nrh + (c << 5) + cs;
#pragma unroll
            for (int j = 0; j < 16; ++j) {
                float v = __bfloat162float(ph[cs + j]) + __bfloat162float(pl[cs + j]);
                den = fmaf(v, nr[j], den);
            }
        }

#pragma unroll
        for (int k16 = 0; k16 < 2; ++k16) {
            uint32_t ah[4][4], al[4][4];
#pragma unroll
            for (int mt = 0; mt < 4; ++mt) {
                uint32_t rowa = (uint32_t)(wm * 64 + mt * 16 + (lane & 15));
                uint32_t coff = (uint32_t)((k16 * 16 + ((lane >> 4) << 3)) * 2);
                ldm_x4(ah[mt], stb + 0 * SK_AT_B + rowa * 80 + coff);
                ldm_x4(al[mt], stb + 1 * SK_AT_B + rowa * 80 + coff);
            }
#pragma unroll
            for (int nt = 0; nt < 4; ++nt) {
                uint32_t rowb = (uint32_t)(k16 * 16 + (lane & 15));
                uint32_t noff = (uint32_t)((wn * 32 + nt * 8) * 2);
                uint32_t bh[2], bl[2];
                ldm_x2_t(bh, stb + 2 * SK_AT_B + 0 * SK_BT_B + rowb * 272 + noff);
                ldm_x2_t(bl, stb + 2 * SK_AT_B + 1 * SK_BT_B + rowb * 272 + noff);
#pragma unroll
                for (int mt = 0; mt < 4; ++mt) {
                    mma_bf16(acc[mt][nt], ah[mt], bh);
                    mma_bf16(acc[mt][nt], ah[mt], bl);
                    mma_bf16(acc[mt][nt], al[mt], bh);
                }
            }
        }
    }

    if (MODE == 1) {
        den += __shfl_xor_sync(0xffffffffu, den, 1);
        if (!(tid & 1)) densm[tid >> 1] = den + EPSV;
        __syncthreads();
    }

    const int r0 = bm + wm * 64;
    const int c0 = wn * 32;
    const int rl = lane >> 2;
    const int cl = (lane & 3) * 2;
#pragma unroll
    for (int mt = 0; mt < 4; ++mt) {
#pragma unroll
        for (int nt = 0; nt < 4; ++nt) {
            int col = c0 + nt * 8 + cl;
#pragma unroll
            for (int half = 0; half < 2; ++half) {
                int row = r0 + mt * 16 + rl + half * 8;
                float n0 = acc[mt][nt][2 * half + 0];
                float n1 = acc[mt][nt][2 * half + 1];
                if (MODE == 0) {
                    // fused weighted_mv
                    float dn = g_DEN[(size_t)h * S + row];
                    float2 v  = *(const float2*)(g_V  + (size_t)row * 512 + (size_t)(h >> 2) * 128 + col);
                    float2 mb = *(const float2*)(g_MB + (size_t)row * HID + (size_t)h * 128 + col);
                    float w0 = (v.x - n0 / dn) * mb.x;
                    float w1 = (v.y - n1 / dn) * mb.y;
                    size_t idx = ((size_t)h * S + row) * DD + col;
                    __nv_bfloat16 h0 = __float2bfloat16(w0), h1 = __float2bfloat16(w1);
                    *(__nv_bfloat162*)(g_WMVH + idx) = __nv_bfloat162(h0, h1);
                    *(__nv_bfloat162*)(g_WMVL + idx) = __nv_bfloat162(
                        __float2bfloat16(w0 - __bfloat162float(h0)),
                        __float2bfloat16(w1 - __bfloat162float(h1)));
                } else {
                    // fused final: out = X + G * (num / den)
                    float dn = densm[wm * 64 + mt * 16 + rl + half * 8];
                    size_t oidx = (size_t)row * HID + (size_t)h * 128 + col;
                    float2 xv = *(const float2*)(Xg + oidx);
                    float2 gv = *(const float2*)(Gg + oidx);
                    float o0 = xv.x + gv.x * (n0 / dn);
                    float o1 = xv.y + gv.y * (n1 / dn);
                    *(float2*)(outg + oidx) = make_float2(o0, o1);
                }
            }
        }
    }
}

// ======================================================================
// Delta GEMM (bf16-split, split-K=4), 3-stage pipeline
// ======================================================================
#define DL_T_B 8704                   // 32 x 272B
#define DL_STAGE (4 * DL_T_B)
#define DL_SMEM  (3 * DL_STAGE)       // 104448

__global__ __launch_bounds__(256, 1) void gemm_delta_mma()
{
    extern __shared__ char sm[];
    const int tid  = threadIdx.x;
    const int lane = tid & 31;
    const int warp = tid >> 5;
    const int wm = warp >> 2;
    const int wn = warp & 3;
    const int h    = blockIdx.z;
    const int part = blockIdx.y;
    const int f0   = blockIdx.x * 128;
    const uint32_t sbase = smem_u32(sm);

    const __nv_bfloat16* Ah = g_MKH + (size_t)(h >> 2) * S * FF;
    const __nv_bfloat16* Al = g_MKL + (size_t)(h >> 2) * S * FF;
    const __nv_bfloat16* Bh = g_WMVH + (size_t)h * S * DD;
    const __nv_bfloat16* Bl = g_WMVL + (size_t)h * S * DD;

    const int kbase = part * (S / 4);

    auto load_chunk = [&](int c, int st) {
        const int k0 = kbase + (c << 5);
        const uint32_t stb = sbase + (uint32_t)st * DL_STAGE;
        const __nv_bfloat16* srcs[4] = {Ah, Al, Bh, Bl};
#pragma unroll
        for (int tile = 0; tile < 4; ++tile) {
            const bool isA = tile < 2;
#pragma unroll
            for (int rep = 0; rep < 2; ++rep) {
                int i = tid + rep * 256;
                int r = i >> 4, cc = i & 15;
                const __nv_bfloat16* src = isA
                    ? srcs[tile] + (size_t)(k0 + r) * FF + f0 + cc * 8
                    : srcs[tile] + (size_t)(k0 + r) * DD + cc * 8;
                cp_async16(stb + (uint32_t)tile * DL_T_B + r * 272 + cc * 16, src);
            }
        }
        cp_commit();
    };

    float acc[4][4][4];
#pragma unroll
    for (int mt = 0; mt < 4; ++mt)
#pragma unroll
        for (int nt = 0; nt < 4; ++nt)
#pragma unroll
            for (int r = 0; r < 4; ++r) acc[mt][nt][r] = 0.f;

    const int NC = (S / 4) >> 5;   // 32
    load_chunk(0, 0);
    load_chunk(1, 1);

    for (int c = 0; c < NC; ++c) {
        if (c + 1 < NC) cp_wait<1>(); else cp_wait<0>();
        __syncthreads();
        if (c + 2 < NC) load_chunk(c + 2, (c + 2) % 3);

        const uint32_t stb = sbase + (uint32_t)(c % 3) * DL_STAGE;
#pragma unroll
        for (int k16 = 0; k16 < 2; ++k16) {
            uint32_t ah[4][4], al[4][4];
            uint32_t rowa = (uint32_t)(k16 * 16 + (lane & 7) + ((lane >> 4) << 3));
#pragma unroll
            for (int mt = 0; mt < 4; ++mt) {
                uint32_t cola = (uint32_t)((wm * 64 + mt * 16 + (((lane >> 3) & 1) << 3)) * 2);
                ldm_x4_t(ah[mt], stb + 0 * DL_T_B + rowa * 272 + cola);
                ldm_x4_t(al[mt], stb + 1 * DL_T_B + rowa * 272 + cola);
            }
#pragma unroll
            for (int nt = 0; nt < 4; ++nt) {
                uint32_t rowb = (uint32_t)(k16 * 16 + (lane & 15));
                uint32_t noff = (uint32_t)((wn * 32 + nt * 8) * 2);
                uint32_t bh[2], bl[2];
                ldm_x2_t(bh, stb + 2 * DL_T_B + rowb * 272 + noff);
                ldm_x2_t(bl, stb + 3 * DL_T_B + rowb * 272 + noff);
#pragma unroll
                for (int mt = 0; mt < 4; ++mt) {
                    mma_bf16(acc[mt][nt], ah[mt], bh);
                    mma_bf16(acc[mt][nt], ah[mt], bl);
                    mma_bf16(acc[mt][nt], al[mt], bh);
                }
            }
        }
    }

    float* Cp = g_DELTA[part] + (size_t)h * FF * DD;
    const int r0 = f0 + wm * 64;
    const int c0 = wn * 32;
    const int rl = lane >> 2;
    const int cl = (lane & 3) * 2;
#pragma unroll
    for (int mt = 0; mt < 4; ++mt)
#pragma unroll
        for (int nt = 0; nt < 4; ++nt) {
            int col = c0 + nt * 8 + cl;
#pragma unroll
            for (int half = 0; half < 2; ++half) {
                int row = r0 + mt * 16 + rl + half * 8;
                *(float2*)(Cp + (size_t)row * DD + col) =
                    make_float2(acc[mt][nt][2 * half], acc[mt][nt][2 * half + 1]);
            }
        }
}

// ======================================================================
// Merged dpfp + L2-normalize (K heads 0-3, Q heads 4-19), bf16 hi/lo out.
// K path fuses denom/coef.
// ======================================================================
__global__ __launch_bounds__(256) void dpfp_all(
    const float* __restrict__ Kp, const float* __restrict__ Qp,
    const float* __restrict__ normv)
{
    const int s  = blockIdx.x;
    const int hh = blockIdx.y;        // 0..19
    const bool isK = hh < NKV;
    const int nh   = isK ? NKV : NH;
    const int head = isK ? hh : hh - NKV;
    const float* X = isK ? Kp : Qp;
    __nv_bfloat16* outh = isK ? g_MKH : g_MQH;
    __nv_bfloat16* outl = isK ? g_MKL : g_MQL;
    const int t  = threadIdx.x;
    __shared__ float y[256];
    __shared__ float red[5][8];

    const float* x = X + ((size_t)s * nh + head) * 128;
    float xv = (t < 128) ? x[t] : -x[t - 128];
    y[t] = fmaxf(xv, 0.f);
    __syncthreads();

    float yi = y[t];
    float m0 = yi * y[(t - 1) & 255];
    float m1 = yi * y[(t - 2) & 255];
    float m2 = yi * y[(t - 3) & 255];
    float ss = m0 * m0 + m1 * m1 + m2 * m2;

    float dd[4];
    if (isK) {
#pragma unroll
        for (int g = 0; g < 4; g++) {
            const float* nr = normv + (size_t)(4 * head + g) * FF;
            dd[g] = m0 * nr[t] + m1 * nr[256 + t] + m2 * nr[512 + t];
        }
    }

    const int lane = t & 31, w = t >> 5;
    float r0 = warp_sum(ss);
    if (lane == 0) red[0][w] = r0;
    if (isK) {
#pragma unroll
        for (int g = 0; g < 4; g++) {
            float rg = warp_sum(dd[g]);
            if (lane == 0) red[1 + g][w] = rg;
        }
    }
    __syncthreads();

    float ssT = 0.f;
#pragma unroll
    for (int w2 = 0; w2 < 8; w2++) ssT += red[0][w2];
    float nrmv = sqrtf(ssT);
    float inv = 1.f / fmaxf(nrmv, 1e-12f);

    size_t base = ((size_t)head * S + s) * FF;
    split_write(m0 * inv, outh, outl, base + t);
    split_write(m1 * inv, outh, outl, base + 256 + t);
    split_write(m2 * inv, outh, outl, base + 512 + t);

    if (isK && t < 4) {
        float dT = 0.f;
#pragma unroll
        for (int w2 = 0; w2 < 8; w2++) dT += red[1 + t][w2];
        float den  = dT * inv + EPSV;
        float mksq = ssT * inv * inv;
        float coef = 1.f - den / mksq;
        coef = fminf(fmaxf(coef, 0.f), 1.f);
        int h = 4 * head + t;
        g_DEN[h * S + s]  = den;
        g_COEF[h * S + s] = coef;
    }
}

// new_norm[h][f] = norm[h][f] + sum_s coef[h][s]*MK[h/4][s][f]   (MK = hi+lo)
__global__ __launch_bounds__(256) void delta_norm_kernel(
    const float* __restrict__ normv, float* __restrict__ out_norm)
{
    const int kv = blockIdx.y;
    const int f0 = blockIdx.x * 64;
    const int t  = threadIdx.x;
    const int fl = t & 63, sl = t >> 6;

    float acc[4] = {0.f, 0.f, 0.f, 0.f};
    const __nv_bfloat16* mh = g_MKH + (size_t)kv * S * FF + f0 + fl;
    const __nv_bfloat16* ml = g_MKL + (size_t)kv * S * FF + f0 + fl;
    for (int s = sl; s < S; s += 4) {
        float v = __bfloat162float(mh[(size_t)s * FF]) + __bfloat162float(ml[(size_t)s * FF]);
#pragma unroll
        for (int g = 0; g < 4; g++)
            acc[g] = fmaf(g_COEF[(4 * kv + g) * S + s], v, acc[g]);
    }
    __shared__ float smr[4][4][64];
#pragma unroll
    for (int g = 0; g < 4; g++) smr[sl][g][fl] = acc[g];
    __syncthreads();
    if (t < 64) {
#pragma unroll
        for (int g = 0; g < 4; g++) {
            float sum = smr[0][g][t] + smr[1][g][t] + smr[2][g][t] + smr[3][g][t];
            int h = 4 * kv + g;
            out_norm[(size_t)h * FF + f0 + t] = normv[(size_t)h * FF + f0 + t] + sum;
        }
    }
}

// new_memory = memory + sum partials; also emit hi/lo bf16
__global__ void add_delta_kernel(const float* __restrict__ memory,
                                 float* __restrict__ out_mem)
{
    size_t idx = (size_t)blockIdx.x * 256 + threadIdx.x;
    float v = memory[idx] + g_DELTA[0][idx] + g_DELTA[1][idx]
            + g_DELTA[2][idx] + g_DELTA[3][idx];
    out_mem[idx] = v;
    split_write(v, g_NMemH, g_NMemL, idx);
}

// ======================================================================
// Launch
// ======================================================================
extern "C" void kernel_launch(void* const* d_in, const int* in_sizes, int n_in,
                              void* d_out, int out_size)
{
    const float* X    = (const float*)d_in[0];
    const float* Wq   = (const float*)d_in[1];
    const float* bq   = (const float*)d_in[2];
    const float* Wk   = (const float*)d_in[3];
    const float* bk   = (const float*)d_in[4];
    const float* Wv   = (const float*)d_in[5];
    const float* bv   = (const float*)d_in[6];
    const float* Wg   = (const float*)d_in[7];
    const float* bg   = (const float*)d_in[8];
    const float* Wmb  = (const float*)d_in[9];
    const float* bmb  = (const float*)d_in[10];
    const float* memv = (const float*)d_in[11];
    const float* normv= (const float*)d_in[12];

    float* out      = (float*)d_out;
    float* out_mem  = out + OUT_ELEMS;
    float* out_norm = out_mem + MEM_ELEMS;

    float *pK, *pV, *pQ, *pMB, *pG;
    cudaGetSymbolAddress((void**)&pK,  g_K);
    cudaGetSymbolAddress((void**)&pV,  g_V);
    cudaGetSymbolAddress((void**)&pQ,  g_Q);
    cudaGetSymbolAddress((void**)&pMB, g_MB);
    cudaGetSymbolAddress((void**)&pG,  g_G);

    __nv_bfloat16 *xh, *xl, *wqh, *wql, *wmh, *wml, *wgh, *wgl, *wkh, *wkl, *wvh, *wvl;
    __nv_bfloat16 *mkh, *mkl, *mqh, *mql, *memh, *meml, *nmh, *nml;
    cudaGetSymbolAddress((void**)&xh,  g_XH);  cudaGetSymbolAddress((void**)&xl,  g_XL);
    cudaGetSymbolAddress((void**)&wqh, g_WqH); cudaGetSymbolAddress((void**)&wql, g_WqL);
    cudaGetSymbolAddress((void**)&wmh, g_WmH); cudaGetSymbolAddress((void**)&wml, g_WmL);
    cudaGetSymbolAddress((void**)&wgh, g_WgH); cudaGetSymbolAddress((void**)&wgl, g_WgL);
    cudaGetSymbolAddress((void**)&wkh, g_WkH); cudaGetSymbolAddress((void**)&wkl, g_WkL);
    cudaGetSymbolAddress((void**)&wvh, g_WvH); cudaGetSymbolAddress((void**)&wvl, g_WvL);
    cudaGetSymbolAddress((void**)&mkh, g_MKH); cudaGetSymbolAddress((void**)&mkl, g_MKL);
    cudaGetSymbolAddress((void**)&mqh, g_MQH); cudaGetSymbolAddress((void**)&mql, g_MQL);
    cudaGetSymbolAddress((void**)&memh, g_MemH); cudaGetSymbolAddress((void**)&meml, g_MemL);
    cudaGetSymbolAddress((void**)&nmh, g_NMemH); cudaGetSymbolAddress((void**)&nml, g_NMemL);

    cudaFuncSetAttribute(gemm_proj, cudaFuncAttributeMaxDynamicSharedMemorySize, PJ_SMEM);
    cudaFuncSetAttribute(gemm_skinny_mma<0>, cudaFuncAttributeMaxDynamicSharedMemorySize, SK_SMEM);
    cudaFuncSetAttribute(gemm_skinny_mma<1>, cudaFuncAttributeMaxDynamicSharedMemorySize, SK_SMEM);
    cudaFuncSetAttribute(gemm_delta_mma, cudaFuncAttributeMaxDynamicSharedMemorySize, DL_SMEM);

    dim3 blk(256);

    // 0) all fp32 -> bf16 hi/lo splits in one launch
    CvtArgs ca;
    ca.s[0] = {X,    xh,  xl,  S * HID / 4};
    ca.s[1] = {Wq,   wqh, wql, HID * HID / 4};
    ca.s[2] = {Wmb,  wmh, wml, HID * HID / 4};
    ca.s[3] = {Wg,   wgh, wgl, HID * HID / 4};
    ca.s[4] = {Wk,   wkh, wkl, 512 * HID / 4};
    ca.s[5] = {Wv,   wvh, wvl, 512 * HID / 4};
    ca.s[6] = {memv, memh, meml, MEM_ELEMS / 4};
    int total4 = ca.s[0].n4 + ca.s[1].n4 + ca.s[2].n4 + ca.s[3].n4
               + ca.s[4].n4 + ca.s[5].n4 + ca.s[6].n4;
    cvt_split_multi<<<(total4 + 255) / 256, blk>>>(ca, total4);

    // 1) all 5 projections in one launch (28 n-blocks x 32 m-blocks)
    ProjArgs pa;
    pa.s[0] = {wqh, wql, bq,  pQ,  HID, 0};
    pa.s[1] = {wmh, wml, bmb, pMB, HID, 1};
    pa.s[2] = {wgh, wgl, bg,  pG,  HID, 1};
    pa.s[3] = {wkh, wkl, bk,  pK,  512, 0};
    pa.s[4] = {wvh, wvl, bv,  pV,  512, 0};
    gemm_proj<<<dim3(28, 32), blk, PJ_SMEM>>>(xh, xl, pa);

    // 2) dpfp + normalize, K and Q merged (K heads fuse denom/coef)
    dpfp_all<<<dim3(S, NKV + NH), blk>>>(pK, pQ, normv);

    // 3) new_norm (needs COEF + MK only)
    delta_norm_kernel<<<dim3(FF / 64, NKV), blk>>>(normv, out_norm);

    // 4) num GEMM with fused weighted_mv epilogue -> WMV hi/lo
    gemm_skinny_mma<0><<<dim3(S / 128, NH), blk, SK_SMEM>>>(
        mkh, mkl, 4, memh, meml, nullptr, nullptr, nullptr, nullptr);

    // 5) delta_memory (split-K=4), then new_memory (+ bf16 split)
    gemm_delta_mma<<<dim3(FF / 128, 4, NH), blk, DL_SMEM>>>();
    add_delta_kernel<<<MEM_ELEMS / 256, blk>>>(memv, out_mem);

    // 6) num_a GEMM with fused den_a + final output epilogue
    gemm_skinny_mma<1><<<dim3(S / 128, NH), blk, SK_SMEM>>>(
        mqh, mql, 1, nmh, nml, out_norm, X, pG, out);
}